// round 7
// baseline (speedup 1.0000x reference)
#include <cuda_runtime.h>
#include <cuda_bf16.h>
#include <cstdint>

#define NN 100000
#define EE 1600000
#define INC 128
#define HIDC 256
#define OUTC 64
#define FEPS 1e-5f
#define NBLK1 ((NN + 255) / 256)

// ---------------- scratch ----------------------------------------------------
__device__ int   g_is64;
__device__ int   g_degi[NN];
__device__ int   g_incl[NN];
__device__ int   g_bsum[512];
__device__ int   g_boff[512];
__device__ int   g_rowptr[NN];
__device__ int   g_cursor[NN];
__device__ int   g_csrc[EE];
__device__ float g_msg[(size_t)NN * HIDC];
__device__ float g_h1[(size_t)NN * HIDC];
__device__ float g_h2[(size_t)NN * HIDC];
__device__ float g_t[(size_t)NN * OUTC];
__device__ float g_r[(size_t)NN * OUTC];
// transposed, split weights, [N][K] layout. Wcl/Wcr contiguous -> one [128][256].
#define WO_1L 0
#define WO_1R 32768
#define WO_2L 65536
#define WO_2R 131072
#define WO_CL 196608
#define WO_CR 212992
__device__ __nv_bfloat16 g_wh[229376];
__device__ __nv_bfloat16 g_wl[229376];

// ---------------- PTX helpers ------------------------------------------------
__device__ __forceinline__ uint32_t smem_u32(const void* p) {
    uint32_t a;
    asm("{ .reg .u64 t; cvta.to.shared.u64 t, %1; cvt.u32.u64 %0, t; }"
        : "=r"(a) : "l"(p));
    return a;
}
#define LDSM4(r, addr)                                                          \
    asm volatile("ldmatrix.sync.aligned.m8n8.x4.shared.b16 {%0,%1,%2,%3}, [%4];"\
                 : "=r"((r)[0]), "=r"((r)[1]), "=r"((r)[2]), "=r"((r)[3])       \
                 : "r"(addr))
#define LDSM2(r, addr)                                                          \
    asm volatile("ldmatrix.sync.aligned.m8n8.x2.shared.b16 {%0,%1}, [%2];"      \
                 : "=r"((r)[0]), "=r"((r)[1]) : "r"(addr))
#define MMA16816(d, a, b)                                                       \
    asm volatile("mma.sync.aligned.m16n8k16.row.col.f32.bf16.bf16.f32 "         \
                 "{%0,%1,%2,%3}, {%4,%5,%6,%7}, {%8,%9}, {%0,%1,%2,%3};"        \
                 : "+f"((d)[0]), "+f"((d)[1]), "+f"((d)[2]), "+f"((d)[3])       \
                 : "r"((a)[0]), "r"((a)[1]), "r"((a)[2]), "r"((a)[3]),          \
                   "r"((b)[0]), "r"((b)[1]))

// ---------------- misc kernels ----------------------------------------------
__device__ __forceinline__ int load_idx(const void* base, long long i) {
    if (g_is64) return (int)((const long long*)base)[i];
    return ((const int*)base)[i];
}
// zero degrees + edge-dtype detection fused
__global__ void k_zero_detect(int* p, int n, const int* e32) {
    int i = blockIdx.x * blockDim.x + threadIdx.x;
    if (i < n) p[i] = 0;
    if (blockIdx.x == 0 && threadIdx.x == 0) {
        int is64 = 1;
        for (int q = 0; q < 32; q++)
            if (e32[2 * q + 1] != 0) is64 = 0;
        g_is64 = is64;
    }
}
__global__ void k_degi(const void* eidx) {
    int e = blockIdx.x * blockDim.x + threadIdx.x;
    if (e < EE) atomicAdd(&g_degi[load_idx(eidx, (long long)EE + e)], 1);
}
__global__ void k_scan1() {
    __shared__ int s[256];
    int i = blockIdx.x * 256 + threadIdx.x;
    int v = (i < NN) ? g_degi[i] : 0;
    s[threadIdx.x] = v;
    __syncthreads();
#pragma unroll
    for (int off = 1; off < 256; off <<= 1) {
        int t = (threadIdx.x >= off) ? s[threadIdx.x - off] : 0;
        __syncthreads();
        s[threadIdx.x] += t;
        __syncthreads();
    }
    if (i < NN) g_incl[i] = s[threadIdx.x];
    if (threadIdx.x == 255) g_bsum[blockIdx.x] = s[255];
}
__global__ void k_scan2() {
    __shared__ int s[512];
    int tid = threadIdx.x;
    s[tid] = (tid < NBLK1) ? g_bsum[tid] : 0;
    __syncthreads();
#pragma unroll
    for (int off = 1; off < 512; off <<= 1) {
        int t = (tid >= off) ? s[tid - off] : 0;
        __syncthreads();
        s[tid] += t;
        __syncthreads();
    }
    g_boff[tid] = s[tid];
}
__global__ void k_scan3() {
    int i = blockIdx.x * 256 + threadIdx.x;
    if (i < NN) {
        int off = (blockIdx.x > 0) ? g_boff[blockIdx.x - 1] : 0;
        int start = off + g_incl[i] - g_degi[i];
        g_rowptr[i] = start;
        g_cursor[i] = start;
    }
}
__global__ void k_fill(const void* eidx) {
    int e = blockIdx.x * blockDim.x + threadIdx.x;
    if (e < EE) {
        int s = load_idx(eidx, e);
        int d = load_idx(eidx, (long long)EE + e);
        g_csrc[atomicAdd(&g_cursor[d], 1)] = s;
    }
}

// ---------------- gather mean aggregation ------------------------------------
template <int CH>
__device__ __forceinline__ void vload(float (&r)[CH], const float* p) {
    if (CH == 2) {
        float2 v = *(const float2*)p;
        r[0] = v.x;
        r[1] = v.y;
    } else {
#pragma unroll
        for (int q = 0; q < CH / 4; q++) {
            float4 v = *(const float4*)(p + q * 4);
            r[q * 4 + 0] = v.x;
            r[q * 4 + 1] = v.y;
            r[q * 4 + 2] = v.z;
            r[q * 4 + 3] = v.w;
        }
    }
}
template <int CH>
__device__ __forceinline__ void vstore(float* p, const float (&r)[CH]) {
    if (CH == 2) {
        *(float2*)p = make_float2(r[0], r[1]);
    } else {
#pragma unroll
        for (int q = 0; q < CH / 4; q++)
            *(float4*)(p + q * 4) =
                make_float4(r[q * 4 + 0], r[q * 4 + 1], r[q * 4 + 2], r[q * 4 + 3]);
    }
}

template <int CH, bool ADD_EXTRA>
__global__ void k_agg(const float* __restrict__ feat,
                      const float* __restrict__ extra,
                      float* __restrict__ outp) {
    const int D = 32 * CH;
    int warp = (blockIdx.x * blockDim.x + threadIdx.x) >> 5;
    int lane = threadIdx.x & 31;
    if (warp >= NN) return;
    int start = g_rowptr[warp];
    int dg = g_degi[warp];
    const float* fb = feat + lane * CH;

    float acc[CH];
#pragma unroll
    for (int v = 0; v < CH; v++) acc[v] = 0.0f;

    int j = 0;
    for (; j + 4 <= dg; j += 4) {
        int s0 = g_csrc[start + j + 0];
        int s1 = g_csrc[start + j + 1];
        int s2 = g_csrc[start + j + 2];
        int s3 = g_csrc[start + j + 3];
        float r0[CH], r1[CH], r2[CH], r3[CH];
        vload<CH>(r0, fb + (long long)s0 * D);
        vload<CH>(r1, fb + (long long)s1 * D);
        vload<CH>(r2, fb + (long long)s2 * D);
        vload<CH>(r3, fb + (long long)s3 * D);
#pragma unroll
        for (int v = 0; v < CH; v++) acc[v] += r0[v];
#pragma unroll
        for (int v = 0; v < CH; v++) acc[v] += r1[v];
#pragma unroll
        for (int v = 0; v < CH; v++) acc[v] += r2[v];
#pragma unroll
        for (int v = 0; v < CH; v++) acc[v] += r3[v];
    }
    for (; j < dg; j++) {
        int s0 = g_csrc[start + j];
        float r0[CH];
        vload<CH>(r0, fb + (long long)s0 * D);
#pragma unroll
        for (int v = 0; v < CH; v++) acc[v] += r0[v];
    }

    float inv = (dg > 0) ? (1.0f / (float)dg) : 0.0f;
    float* op = outp + (long long)warp * D + lane * CH;
#pragma unroll
    for (int v = 0; v < CH; v++) acc[v] *= inv;
    if (ADD_EXTRA) {
        float ex[CH];
        vload<CH>(ex, extra + (long long)warp * D + lane * CH);
#pragma unroll
        for (int v = 0; v < CH; v++) acc[v] += ex[v];
    }
    vstore<CH>(op, acc);
}

// W[K,N] fp32 -> Wt[N,K] bf16 hi/lo
__global__ void k_wsplit(const float* __restrict__ W,
                         __nv_bfloat16* __restrict__ th,
                         __nv_bfloat16* __restrict__ tl, int K, int N) {
    int i = blockIdx.x * blockDim.x + threadIdx.x;
    if (i < K * N) {
        int k = i / N, n = i % N;
        float v = W[i];
        __nv_bfloat16 h = __float2bfloat16(v);
        th[n * K + k] = h;
        tl[n * K + k] = __float2bfloat16(v - __bfloat162float(h));
    }
}

// ---------------- mma.sync bf16-split GEMM, BM=128 BN=128, double-buffered ---
// 8 warps (4m x 2n), warp tile 32x64 = 2 m-atoms x 8 n-atoms.
#define ASTR 40
#define OAH 0
#define OAL 10240        // 128*ASTR*2
#define OBH 20480
#define OBL 30720
#define BUFB 40960       // per stage
template <int KTOT, int NOUT, int NMAT, bool HAS_BIAS, bool BN, bool DUAL>
__global__ void __launch_bounds__(256) k_mgemm(
    const float* __restrict__ A1, const float* __restrict__ A2,
    const __nv_bfloat16* __restrict__ B1h, const __nv_bfloat16* __restrict__ B1l,
    const __nv_bfloat16* __restrict__ B2h, const __nv_bfloat16* __restrict__ B2l,
    const float* __restrict__ bias, const float* __restrict__ gamma,
    const float* __restrict__ beta, const float* __restrict__ rm,
    const float* __restrict__ rv, float* __restrict__ C1,
    float* __restrict__ C2) {
    extern __shared__ __align__(16) char dsm[];

    const int tid = threadIdx.x;
    const int lane = tid & 31;
    const int wid = tid >> 5;
    const int wm = wid & 3;   // 4 m-warps: 32 rows each
    const int wn = wid >> 2;  // 2 n-warps: 64 cols each
    const long long bm = (long long)blockIdx.x * 128;
    const int bn = blockIdx.y * 128;
    const int KC = KTOT / 32;
    const int TOT = NMAT * KC;

    float acc[2][8][4];
#pragma unroll
    for (int i = 0; i < 2; i++)
#pragma unroll
        for (int j = 0; j < 8; j++)
#pragma unroll
            for (int q = 0; q < 4; q++) acc[i][j][q] = 0.0f;

    const uint32_t sb = smem_u32(dsm);
    const uint32_t loA = (((wm * 32 + (lane & 15)) * ASTR + ((lane >> 4) << 3)) << 1);
    const uint32_t loB = (((wn * 64 + (lane & 7)) * ASTR + (((lane >> 3) & 1) << 3)) << 1);

    float4 aR[4];
    uint4 bhR[2], blR[2];

#define LOAD_ITER(it) do {                                                       \
    int _m = (it) / KC, _kc = (it) % KC, _k0 = _kc * 32;                         \
    const float* _A = (_m == 0) ? A1 : A2;                                       \
    const __nv_bfloat16* _Bh = (_m == 0) ? B1h : B2h;                            \
    const __nv_bfloat16* _Bl = (_m == 0) ? B1l : B2l;                            \
    _Pragma("unroll")                                                            \
    for (int _i = 0; _i < 4; _i++) {                                             \
        int _s = tid + _i * 256;                                                 \
        int _r = _s >> 3, _c = _s & 7;                                           \
        long long _grow = bm + _r;                                               \
        float4 _v = make_float4(0.f, 0.f, 0.f, 0.f);                             \
        if (_grow < NN) _v = *(const float4*)(_A + _grow * KTOT + _k0 + _c * 4); \
        aR[_i] = _v;                                                             \
    }                                                                            \
    _Pragma("unroll")                                                            \
    for (int _i = 0; _i < 2; _i++) {                                             \
        int _s = tid + _i * 256;                                                 \
        int _r = _s >> 2, _c = _s & 3;                                           \
        long long _off = (long long)(bn + _r) * KTOT + _k0 + _c * 8;             \
        bhR[_i] = *(const uint4*)(_Bh + _off);                                   \
        blR[_i] = *(const uint4*)(_Bl + _off);                                   \
    }                                                                            \
} while (0)

#define STORE_ITER(buf) do {                                                     \
    char* _S = dsm + (buf) * BUFB;                                               \
    _Pragma("unroll")                                                            \
    for (int _i = 0; _i < 4; _i++) {                                             \
        int _s = tid + _i * 256;                                                 \
        int _r = _s >> 3, _c = _s & 7;                                           \
        float _f[4] = {aR[_i].x, aR[_i].y, aR[_i].z, aR[_i].w};                  \
        uint32_t _h01, _h23, _l01, _l23;                                         \
        {                                                                        \
            __nv_bfloat16 _h0 = __float2bfloat16(_f[0]);                         \
            __nv_bfloat16 _h1 = __float2bfloat16(_f[1]);                         \
            __nv_bfloat16 _h2 = __float2bfloat16(_f[2]);                         \
            __nv_bfloat16 _h3 = __float2bfloat16(_f[3]);                         \
            __nv_bfloat16 _l0 = __float2bfloat16(_f[0] - __bfloat162float(_h0)); \
            __nv_bfloat16 _l1 = __float2bfloat16(_f[1] - __bfloat162float(_h1)); \
            __nv_bfloat16 _l2 = __float2bfloat16(_f[2] - __bfloat162float(_h2)); \
            __nv_bfloat16 _l3 = __float2bfloat16(_f[3] - __bfloat162float(_h3)); \
            _h01 = ((uint32_t)__bfloat16_as_ushort(_h1) << 16) |                 \
                   __bfloat16_as_ushort(_h0);                                    \
            _h23 = ((uint32_t)__bfloat16_as_ushort(_h3) << 16) |                 \
                   __bfloat16_as_ushort(_h2);                                    \
            _l01 = ((uint32_t)__bfloat16_as_ushort(_l1) << 16) |                 \
                   __bfloat16_as_ushort(_l0);                                    \
            _l23 = ((uint32_t)__bfloat16_as_ushort(_l3) << 16) |                 \
                   __bfloat16_as_ushort(_l2);                                    \
        }                                                                        \
        *(uint2*)(_S + OAH + (_r * ASTR + _c * 4) * 2) = make_uint2(_h01, _h23); \
        *(uint2*)(_S + OAL + (_r * ASTR + _c * 4) * 2) = make_uint2(_l01, _l23); \
    }                                                                            \
    _Pragma("unroll")                                                            \
    for (int _i = 0; _i < 2; _i++) {                                             \
        int _s = tid + _i * 256;                                                 \
        int _r = _s >> 2, _c = _s & 3;                                           \
        *(uint4*)(_S + OBH + (_r * ASTR + _c * 8) * 2) = bhR[_i];                \
        *(uint4*)(_S + OBL + (_r * ASTR + _c * 8) * 2) = blR[_i];                \
    }                                                                            \
} while (0)

#define COMPUTE(buf) do {                                                        \
    const uint32_t _b = sb + (buf) * BUFB;                                       \
    const uint32_t _aAh = _b + OAH + loA;                                        \
    const uint32_t _aAl = _b + OAL + loA;                                        \
    const uint32_t _aBh = _b + OBH + loB;                                        \
    const uint32_t _aBl = _b + OBL + loB;                                        \
    _Pragma("unroll")                                                            \
    for (int _ka = 0; _ka < 2; _ka++) {                                          \
        const uint32_t _ko = _ka * 32;                                           \
        uint32_t _ah[2][4], _al[2][4], _bh[8][2], _bl[8][2];                     \
        LDSM4(_ah[0], _aAh + _ko);                                               \
        LDSM4(_ah[1], _aAh + 1280 + _ko);                                        \
        LDSM4(_al[0], _aAl + _ko);                                               \
        LDSM4(_al[1], _aAl + 1280 + _ko);                                        \
        _Pragma("unroll")                                                        \
        for (int _na = 0; _na < 8; _na++) {                                      \
            LDSM2(_bh[_na], _aBh + _na * 640 + _ko);                             \
            LDSM2(_bl[_na], _aBl + _na * 640 + _ko);                             \
        }                                                                        \
        _Pragma("unroll")                                                        \
        for (int _ma = 0; _ma < 2; _ma++)                                        \
            _Pragma("unroll")                                                    \
            for (int _na = 0; _na < 8; _na++) {                                  \
                MMA16816(acc[_ma][_na], _ah[_ma], _bh[_na]);                     \
                MMA16816(acc[_ma][_na], _ah[_ma], _bl[_na]);                     \
                MMA16816(acc[_ma][_na], _al[_ma], _bh[_na]);                     \
            }                                                                    \
    }                                                                            \
} while (0)

    LOAD_ITER(0);
    STORE_ITER(0);
    __syncthreads();
    for (int it = 0; it < TOT; it++) {
        const int cur = it & 1;
        if (it + 1 < TOT) LOAD_ITER(it + 1);
        COMPUTE(cur);
        if (it + 1 < TOT) STORE_ITER(cur ^ 1);
        __syncthreads();
    }

    // epilogue
    const int g = lane >> 2, t = lane & 3;
#pragma unroll
    for (int ma = 0; ma < 2; ma++) {
#pragma unroll
        for (int na = 0; na < 8; na++) {
            int lcol = wn * 64 + na * 8 + 2 * t;
            int gc = bn + lcol;
#pragma unroll
            for (int half = 0; half < 2; half++) {
                long long row = bm + wm * 32 + ma * 16 + g + half * 8;
                if (row >= NN) continue;
                float v0 = acc[ma][na][half * 2 + 0];
                float v1 = acc[ma][na][half * 2 + 1];
                if (DUAL) {
                    if (gc < 64) {
                        C1[row * 64 + gc] = v0;
                        C1[row * 64 + gc + 1] = v1;
                    } else {
                        C2[row * 64 + gc - 64] = v0 + bias[gc - 64];
                        C2[row * 64 + gc - 63] = v1 + bias[gc - 63];
                    }
                } else {
                    if (HAS_BIAS) { v0 += bias[gc]; v1 += bias[gc + 1]; }
                    if (BN) {
                        v0 = (v0 - rm[gc]) * rsqrtf(rv[gc] + FEPS) * gamma[gc] + beta[gc];
                        v1 = (v1 - rm[gc + 1]) * rsqrtf(rv[gc + 1] + FEPS) * gamma[gc + 1] + beta[gc + 1];
                        v0 = fmaxf(v0, 0.0f);
                        v1 = fmaxf(v1, 0.0f);
                    }
                    C1[row * NOUT + gc] = v0;
                    C1[row * NOUT + gc + 1] = v1;
                }
            }
        }
    }
#undef LOAD_ITER
#undef STORE_ITER
#undef COMPUTE
}

// ---------------- launch ----------------------------------------------------
extern "C" void kernel_launch(void* const* d_in, const int* in_sizes, int n_in,
                              void* d_out, int out_size) {
    const float* x    = (const float*)d_in[0];
    const void*  eidx = d_in[1];
    const float* W1l  = (const float*)d_in[2];
    const float* b1l  = (const float*)d_in[3];
    const float* W1r  = (const float*)d_in[4];
    const float* g1   = (const float*)d_in[5];
    const float* be1  = (const float*)d_in[6];
    const float* rm1  = (const float*)d_in[7];
    const float* rv1  = (const float*)d_in[8];
    const float* W2l  = (const float*)d_in[9];
    const float* b2l  = (const float*)d_in[10];
    const float* W2r  = (const float*)d_in[11];
    const float* g2   = (const float*)d_in[12];
    const float* be2  = (const float*)d_in[13];
    const float* rm2  = (const float*)d_in[14];
    const float* rv2  = (const float*)d_in[15];
    const float* Wcl  = (const float*)d_in[16];
    const float* bcl  = (const float*)d_in[17];
    const float* Wcr  = (const float*)d_in[18];
    float* out = (float*)d_out;

    int* p_degi;        cudaGetSymbolAddress((void**)&p_degi, g_degi);
    float* p_msg;       cudaGetSymbolAddress((void**)&p_msg, g_msg);
    float* p_h1;        cudaGetSymbolAddress((void**)&p_h1, g_h1);
    float* p_h2;        cudaGetSymbolAddress((void**)&p_h2, g_h2);
    float* p_t;         cudaGetSymbolAddress((void**)&p_t, g_t);
    float* p_r;         cudaGetSymbolAddress((void**)&p_r, g_r);
    __nv_bfloat16* wh;  cudaGetSymbolAddress((void**)&wh, g_wh);
    __nv_bfloat16* wl;  cudaGetSymbolAddress((void**)&wl, g_wl);

    const int DSMEM = 2 * BUFB;  // 81920
    cudaFuncSetAttribute(k_mgemm<INC, HIDC, 2, true, true, false>,
                         cudaFuncAttributeMaxDynamicSharedMemorySize, DSMEM);
    cudaFuncSetAttribute(k_mgemm<HIDC, HIDC, 2, true, true, false>,
                         cudaFuncAttributeMaxDynamicSharedMemorySize, DSMEM);
    cudaFuncSetAttribute(k_mgemm<HIDC, 128, 1, true, false, true>,
                         cudaFuncAttributeMaxDynamicSharedMemorySize, DSMEM);

    // 0) CSR build (detect fused into zero)
    k_zero_detect<<<NBLK1, 256>>>(p_degi, NN, (const int*)eidx);
    k_degi<<<(EE + 255) / 256, 256>>>(eidx);
    k_scan1<<<NBLK1, 256>>>();
    k_scan2<<<1, 512>>>();
    k_scan3<<<NBLK1, 256>>>();
    k_fill<<<(EE + 255) / 256, 256>>>(eidx);

    // 1) weight transpose + split
    k_wsplit<<<(INC * HIDC + 255) / 256, 256>>>(W1l, wh + WO_1L, wl + WO_1L, INC, HIDC);
    k_wsplit<<<(INC * HIDC + 255) / 256, 256>>>(W1r, wh + WO_1R, wl + WO_1R, INC, HIDC);
    k_wsplit<<<(HIDC * HIDC + 255) / 256, 256>>>(W2l, wh + WO_2L, wl + WO_2L, HIDC, HIDC);
    k_wsplit<<<(HIDC * HIDC + 255) / 256, 256>>>(W2r, wh + WO_2R, wl + WO_2R, HIDC, HIDC);
    k_wsplit<<<(HIDC * OUTC + 255) / 256, 256>>>(Wcl, wh + WO_CL, wl + WO_CL, HIDC, OUTC);
    k_wsplit<<<(HIDC * OUTC + 255) / 256, 256>>>(Wcr, wh + WO_CR, wl + WO_CR, HIDC, OUTC);

    const int MBLK = (NN + 127) / 128;  // 782
    const int AGG_BLOCKS = (NN + 7) / 8;

    // 2) layer 1: agg -> GEMM(+BN+ReLU)
    k_agg<INC / 32, false><<<AGG_BLOCKS, 256>>>(x, nullptr, p_msg);
    k_mgemm<INC, HIDC, 2, true, true, false><<<dim3(MBLK, HIDC / 128), 256, DSMEM>>>(
        p_msg, x, wh + WO_1L, wl + WO_1L, wh + WO_1R, wl + WO_1R,
        b1l, g1, be1, rm1, rv1, p_h1, nullptr);

    // 3) layer 2
    k_agg<HIDC / 32, false><<<AGG_BLOCKS, 256>>>(p_h1, nullptr, p_msg);
    k_mgemm<HIDC, HIDC, 2, true, true, false><<<dim3(MBLK, HIDC / 128), 256, DSMEM>>>(
        p_msg, p_h1, wh + WO_2L, wl + WO_2L, wh + WO_2R, wl + WO_2R,
        b2l, g2, be2, rm2, rv2, p_h2, nullptr);

    // 4) layer 3: dual GEMM (t = h2@Wcl, r = h2@Wcr + bcl), then out = agg(t)+r
    k_mgemm<HIDC, 128, 1, true, false, true><<<dim3(MBLK, 1), 256, DSMEM>>>(
        p_h2, nullptr, wh + WO_CL, wl + WO_CL, nullptr, nullptr,
        bcl, nullptr, nullptr, nullptr, nullptr, p_t, p_r);
    k_agg<OUTC / 32, true><<<AGG_BLOCKS, 256>>>(p_t, p_r, out);
}

// round 8
// speedup vs baseline: 1.0963x; 1.0963x over previous
#include <cuda_runtime.h>
#include <cuda_bf16.h>
#include <cstdint>

#define NN 100000
#define EE 1600000
#define INC 128
#define HIDC 256
#define OUTC 64
#define FEPS 1e-5f
#define NBLK1 ((NN + 255) / 256)

// ---------------- scratch ----------------------------------------------------
__device__ int   g_is64;
__device__ int   g_degi[NN];
__device__ int   g_incl[NN];
__device__ int   g_bsum[512];
__device__ int   g_boff[512];
__device__ int   g_rowptr[NN];
__device__ int   g_cursor[NN];
__device__ int   g_csrc[EE];
__device__ float g_msg[(size_t)NN * HIDC];
__device__ float g_h1[(size_t)NN * HIDC];
__device__ float g_h2[(size_t)NN * HIDC];
__device__ float g_t[(size_t)NN * OUTC];
__device__ float g_r[(size_t)NN * OUTC];
// transposed, split weights, [N][K] layout.
#define WO_1L 0
#define WO_1R 32768
#define WO_2L 65536
#define WO_2R 131072
#define WO_CL 196608
#define WO_CR 212992
__device__ __nv_bfloat16 g_wh[229376];
__device__ __nv_bfloat16 g_wl[229376];

// ---------------- PTX helpers ------------------------------------------------
__device__ __forceinline__ uint32_t smem_u32(const void* p) {
    uint32_t a;
    asm("{ .reg .u64 t; cvta.to.shared.u64 t, %1; cvt.u32.u64 %0, t; }"
        : "=r"(a) : "l"(p));
    return a;
}
#define LDSM4(r, addr)                                                          \
    asm volatile("ldmatrix.sync.aligned.m8n8.x4.shared.b16 {%0,%1,%2,%3}, [%4];"\
                 : "=r"((r)[0]), "=r"((r)[1]), "=r"((r)[2]), "=r"((r)[3])       \
                 : "r"(addr))
#define LDSM2(r, addr)                                                          \
    asm volatile("ldmatrix.sync.aligned.m8n8.x2.shared.b16 {%0,%1}, [%2];"      \
                 : "=r"((r)[0]), "=r"((r)[1]) : "r"(addr))
#define MMA16816(d, a, b)                                                       \
    asm volatile("mma.sync.aligned.m16n8k16.row.col.f32.bf16.bf16.f32 "         \
                 "{%0,%1,%2,%3}, {%4,%5,%6,%7}, {%8,%9}, {%0,%1,%2,%3};"        \
                 : "+f"((d)[0]), "+f"((d)[1]), "+f"((d)[2]), "+f"((d)[3])       \
                 : "r"((a)[0]), "r"((a)[1]), "r"((a)[2]), "r"((a)[3]),          \
                   "r"((b)[0]), "r"((b)[1]))

// ---------------- misc kernels ----------------------------------------------
__device__ __forceinline__ int load_idx(const void* base, long long i) {
    if (g_is64) return (int)((const long long*)base)[i];
    return ((const int*)base)[i];
}
__global__ void k_zero_detect(int* p, int n, const int* e32) {
    int i = blockIdx.x * blockDim.x + threadIdx.x;
    if (i < n) p[i] = 0;
    if (blockIdx.x == 0 && threadIdx.x == 0) {
        int is64 = 1;
        for (int q = 0; q < 32; q++)
            if (e32[2 * q + 1] != 0) is64 = 0;
        g_is64 = is64;
    }
}
__global__ void k_degi(const void* eidx) {
    int e = blockIdx.x * blockDim.x + threadIdx.x;
    if (e < EE) atomicAdd(&g_degi[load_idx(eidx, (long long)EE + e)], 1);
}
__global__ void k_scan1() {
    __shared__ int s[256];
    int i = blockIdx.x * 256 + threadIdx.x;
    int v = (i < NN) ? g_degi[i] : 0;
    s[threadIdx.x] = v;
    __syncthreads();
#pragma unroll
    for (int off = 1; off < 256; off <<= 1) {
        int t = (threadIdx.x >= off) ? s[threadIdx.x - off] : 0;
        __syncthreads();
        s[threadIdx.x] += t;
        __syncthreads();
    }
    if (i < NN) g_incl[i] = s[threadIdx.x];
    if (threadIdx.x == 255) g_bsum[blockIdx.x] = s[255];
}
__global__ void k_scan2() {
    __shared__ int s[512];
    int tid = threadIdx.x;
    s[tid] = (tid < NBLK1) ? g_bsum[tid] : 0;
    __syncthreads();
#pragma unroll
    for (int off = 1; off < 512; off <<= 1) {
        int t = (tid >= off) ? s[tid - off] : 0;
        __syncthreads();
        s[tid] += t;
        __syncthreads();
    }
    g_boff[tid] = s[tid];
}
__global__ void k_scan3() {
    int i = blockIdx.x * 256 + threadIdx.x;
    if (i < NN) {
        int off = (blockIdx.x > 0) ? g_boff[blockIdx.x - 1] : 0;
        int start = off + g_incl[i] - g_degi[i];
        g_rowptr[i] = start;
        g_cursor[i] = start;
    }
}
__global__ void k_fill(const void* eidx) {
    int e = blockIdx.x * blockDim.x + threadIdx.x;
    if (e < EE) {
        int s = load_idx(eidx, e);
        int d = load_idx(eidx, (long long)EE + e);
        g_csrc[atomicAdd(&g_cursor[d], 1)] = s;
    }
}

// ---------------- gather mean aggregation ------------------------------------
// WPN warps cooperate on one node; each warp owns 32*CH contiguous channels.
template <int CH>
__device__ __forceinline__ void vload(float (&r)[CH], const float* p) {
    if (CH == 2) {
        float2 v = *(const float2*)p;
        r[0] = v.x;
        r[1] = v.y;
    } else {
#pragma unroll
        for (int q = 0; q < CH / 4; q++) {
            float4 v = *(const float4*)(p + q * 4);
            r[q * 4 + 0] = v.x;
            r[q * 4 + 1] = v.y;
            r[q * 4 + 2] = v.z;
            r[q * 4 + 3] = v.w;
        }
    }
}
template <int CH>
__device__ __forceinline__ void vstore(float* p, const float (&r)[CH]) {
    if (CH == 2) {
        *(float2*)p = make_float2(r[0], r[1]);
    } else {
#pragma unroll
        for (int q = 0; q < CH / 4; q++)
            *(float4*)(p + q * 4) =
                make_float4(r[q * 4 + 0], r[q * 4 + 1], r[q * 4 + 2], r[q * 4 + 3]);
    }
}

template <int CH, int WPN, bool ADD_EXTRA>
__global__ void k_agg(const float* __restrict__ feat,
                      const float* __restrict__ extra,
                      float* __restrict__ outp) {
    const int D = 32 * CH * WPN;
    int warp = (blockIdx.x * blockDim.x + threadIdx.x) >> 5;
    int lane = threadIdx.x & 31;
    int node = warp / WPN;
    int sub = warp % WPN;
    if (node >= NN) return;
    int start = g_rowptr[node];
    int dg = g_degi[node];
    const int base = sub * 32 * CH + lane * CH;
    const float* fb = feat + base;

    float acc[CH];
#pragma unroll
    for (int v = 0; v < CH; v++) acc[v] = 0.0f;

    int j = 0;
    for (; j + 4 <= dg; j += 4) {
        int s0 = g_csrc[start + j + 0];
        int s1 = g_csrc[start + j + 1];
        int s2 = g_csrc[start + j + 2];
        int s3 = g_csrc[start + j + 3];
        float r0[CH], r1[CH], r2[CH], r3[CH];
        vload<CH>(r0, fb + (long long)s0 * D);
        vload<CH>(r1, fb + (long long)s1 * D);
        vload<CH>(r2, fb + (long long)s2 * D);
        vload<CH>(r3, fb + (long long)s3 * D);
#pragma unroll
        for (int v = 0; v < CH; v++) acc[v] += r0[v];
#pragma unroll
        for (int v = 0; v < CH; v++) acc[v] += r1[v];
#pragma unroll
        for (int v = 0; v < CH; v++) acc[v] += r2[v];
#pragma unroll
        for (int v = 0; v < CH; v++) acc[v] += r3[v];
    }
    for (; j < dg; j++) {
        int s0 = g_csrc[start + j];
        float r0[CH];
        vload<CH>(r0, fb + (long long)s0 * D);
#pragma unroll
        for (int v = 0; v < CH; v++) acc[v] += r0[v];
    }

    float inv = (dg > 0) ? (1.0f / (float)dg) : 0.0f;
    float* op = outp + (long long)node * D + base;
#pragma unroll
    for (int v = 0; v < CH; v++) acc[v] *= inv;
    if (ADD_EXTRA) {
        float ex[CH];
        vload<CH>(ex, extra + (long long)node * D + base);
#pragma unroll
        for (int v = 0; v < CH; v++) acc[v] += ex[v];
    }
    vstore<CH>(op, acc);
}

// W[K,N] fp32 -> Wt[N,K] bf16 hi/lo
__global__ void k_wsplit(const float* __restrict__ W,
                         __nv_bfloat16* __restrict__ th,
                         __nv_bfloat16* __restrict__ tl, int K, int N) {
    int i = blockIdx.x * blockDim.x + threadIdx.x;
    if (i < K * N) {
        int k = i / N, n = i % N;
        float v = W[i];
        __nv_bfloat16 h = __float2bfloat16(v);
        th[n * K + k] = h;
        tl[n * K + k] = __float2bfloat16(v - __bfloat162float(h));
    }
}

// ---------------- mma.sync bf16-split GEMM, BM=128 BN=64, double-buffered ----
// (round-6 proven configuration)
#define ASTR 40
#define OAH 0
#define OAL 10240
#define OBH 20480
#define OBL 25600
#define BUFB 30720
template <int KTOT, int NOUT, int NMAT, bool HAS_BIAS, bool BN, bool DUAL>
__global__ void __launch_bounds__(256) k_mgemm(
    const float* __restrict__ A1, const float* __restrict__ A2,
    const __nv_bfloat16* __restrict__ B1h, const __nv_bfloat16* __restrict__ B1l,
    const __nv_bfloat16* __restrict__ B2h, const __nv_bfloat16* __restrict__ B2l,
    const float* __restrict__ bias, const float* __restrict__ gamma,
    const float* __restrict__ beta, const float* __restrict__ rm,
    const float* __restrict__ rv, float* __restrict__ C1,
    float* __restrict__ C2) {
    extern __shared__ __align__(16) char dsm[];

    const int tid = threadIdx.x;
    const int lane = tid & 31;
    const int wid = tid >> 5;
    const int wm = wid & 3;
    const int wn = wid >> 2;
    const long long bm = (long long)blockIdx.x * 128;
    const int bn = blockIdx.y * 64;
    const int KC = KTOT / 32;
    const int TOT = NMAT * KC;

    float acc[2][4][4];
#pragma unroll
    for (int i = 0; i < 2; i++)
#pragma unroll
        for (int j = 0; j < 4; j++)
#pragma unroll
            for (int q = 0; q < 4; q++) acc[i][j][q] = 0.0f;

    const uint32_t sb = smem_u32(dsm);
    const uint32_t loA = (((wm * 32 + (lane & 15)) * ASTR + ((lane >> 4) << 3)) << 1);
    const uint32_t loB = (((wn * 32 + (lane & 7)) * ASTR + (((lane >> 3) & 1) << 3)) << 1);

    float4 aR[4];
    uint4 bhR, blR;

#define LOAD_ITER(it) do {                                                       \
    int _m = (it) / KC, _kc = (it) % KC, _k0 = _kc * 32;                         \
    const float* _A = (_m == 0) ? A1 : A2;                                       \
    const __nv_bfloat16* _Bh = (_m == 0) ? B1h : B2h;                            \
    const __nv_bfloat16* _Bl = (_m == 0) ? B1l : B2l;                            \
    _Pragma("unroll")                                                            \
    for (int _i = 0; _i < 4; _i++) {                                             \
        int _s = tid + _i * 256;                                                 \
        int _r = _s >> 3, _c = _s & 7;                                           \
        long long _grow = bm + _r;                                               \
        float4 _v = make_float4(0.f, 0.f, 0.f, 0.f);                             \
        if (_grow < NN) _v = *(const float4*)(_A + _grow * KTOT + _k0 + _c * 4); \
        aR[_i] = _v;                                                             \
    }                                                                            \
    {                                                                            \
        int _r = tid >> 2, _c = tid & 3;                                         \
        long long _off = (long long)(bn + _r) * KTOT + _k0 + _c * 8;             \
        bhR = *(const uint4*)(_Bh + _off);                                       \
        blR = *(const uint4*)(_Bl + _off);                                       \
    }                                                                            \
} while (0)

#define STORE_ITER(buf) do {                                                     \
    char* _S = dsm + (buf) * BUFB;                                               \
    _Pragma("unroll")                                                            \
    for (int _i = 0; _i < 4; _i++) {                                             \
        int _s = tid + _i * 256;                                                 \
        int _r = _s >> 3, _c = _s & 7;                                           \
        float _f[4] = {aR[_i].x, aR[_i].y, aR[_i].z, aR[_i].w};                  \
        uint32_t _h01, _h23, _l01, _l23;                                         \
        {                                                                        \
            __nv_bfloat16 _h0 = __float2bfloat16(_f[0]);                         \
            __nv_bfloat16 _h1 = __float2bfloat16(_f[1]);                         \
            __nv_bfloat16 _h2 = __float2bfloat16(_f[2]);                         \
            __nv_bfloat16 _h3 = __float2bfloat16(_f[3]);                         \
            __nv_bfloat16 _l0 = __float2bfloat16(_f[0] - __bfloat162float(_h0)); \
            __nv_bfloat16 _l1 = __float2bfloat16(_f[1] - __bfloat162float(_h1)); \
            __nv_bfloat16 _l2 = __float2bfloat16(_f[2] - __bfloat162float(_h2)); \
            __nv_bfloat16 _l3 = __float2bfloat16(_f[3] - __bfloat162float(_h3)); \
            _h01 = ((uint32_t)__bfloat16_as_ushort(_h1) << 16) |                 \
                   __bfloat16_as_ushort(_h0);                                    \
            _h23 = ((uint32_t)__bfloat16_as_ushort(_h3) << 16) |                 \
                   __bfloat16_as_ushort(_h2);                                    \
            _l01 = ((uint32_t)__bfloat16_as_ushort(_l1) << 16) |                 \
                   __bfloat16_as_ushort(_l0);                                    \
            _l23 = ((uint32_t)__bfloat16_as_ushort(_l3) << 16) |                 \
                   __bfloat16_as_ushort(_l2);                                    \
        }                                                                        \
        *(uint2*)(_S + OAH + (_r * ASTR + _c * 4) * 2) = make_uint2(_h01, _h23); \
        *(uint2*)(_S + OAL + (_r * ASTR + _c * 4) * 2) = make_uint2(_l01, _l23); \
    }                                                                            \
    {                                                                            \
        int _r = tid >> 2, _c = tid & 3;                                         \
        *(uint4*)(_S + OBH + (_r * ASTR + _c * 8) * 2) = bhR;                    \
        *(uint4*)(_S + OBL + (_r * ASTR + _c * 8) * 2) = blR;                    \
    }                                                                            \
} while (0)

#define COMPUTE(buf) do {                                                        \
    const uint32_t _b = sb + (buf) * BUFB;                                       \
    const uint32_t _aAh = _b + OAH + loA;                                        \
    const uint32_t _aAl = _b + OAL + loA;                                        \
    const uint32_t _aBh = _b + OBH + loB;                                        \
    const uint32_t _aBl = _b + OBL + loB;                                        \
    _Pragma("unroll")                                                            \
    for (int _ka = 0; _ka < 2; _ka++) {                                          \
        const uint32_t _ko = _ka * 32;                                           \
        uint32_t _ah[2][4], _al[2][4], _bh[4][2], _bl[4][2];                     \
        LDSM4(_ah[0], _aAh + _ko);                                               \
        LDSM4(_ah[1], _aAh + 1280 + _ko);                                        \
        LDSM4(_al[0], _aAl + _ko);                                               \
        LDSM4(_al[1], _aAl + 1280 + _ko);                                        \
        _Pragma("unroll")                                                        \
        for (int _na = 0; _na < 4; _na++) {                                      \
            LDSM2(_bh[_na], _aBh + _na * 640 + _ko);                             \
            LDSM2(_bl[_na], _aBl + _na * 640 + _ko);                             \
        }                                                                        \
        _Pragma("unroll")                                                        \
        for (int _ma = 0; _ma < 2; _ma++)                                        \
            _Pragma("unroll")                                                    \
            for (int _na = 0; _na < 4; _na++) {                                  \
                MMA16816(acc[_ma][_na], _ah[_ma], _bh[_na]);                     \
                MMA16816(acc[_ma][_na], _ah[_ma], _bl[_na]);                     \
                MMA16816(acc[_ma][_na], _al[_ma], _bh[_na]);                     \
            }                                                                    \
    }                                                                            \
} while (0)

    LOAD_ITER(0);
    STORE_ITER(0);
    __syncthreads();
    for (int it = 0; it < TOT; it++) {
        const int cur = it & 1;
        if (it + 1 < TOT) LOAD_ITER(it + 1);
        COMPUTE(cur);
        if (it + 1 < TOT) STORE_ITER(cur ^ 1);
        __syncthreads();
    }

    const int g = lane >> 2, t = lane & 3;
#pragma unroll
    for (int ma = 0; ma < 2; ma++) {
#pragma unroll
        for (int na = 0; na < 4; na++) {
            int lcol = wn * 32 + na * 8 + 2 * t;
            int gc = bn + lcol;
#pragma unroll
            for (int half = 0; half < 2; half++) {
                long long row = bm + wm * 32 + ma * 16 + g + half * 8;
                if (row >= NN) continue;
                float v0 = acc[ma][na][half * 2 + 0];
                float v1 = acc[ma][na][half * 2 + 1];
                if (DUAL) {
                    if (gc < 64) {
                        C1[row * 64 + gc] = v0;
                        C1[row * 64 + gc + 1] = v1;
                    } else {
                        C2[row * 64 + gc - 64] = v0 + bias[gc - 64];
                        C2[row * 64 + gc - 63] = v1 + bias[gc - 63];
                    }
                } else {
                    if (HAS_BIAS) { v0 += bias[gc]; v1 += bias[gc + 1]; }
                    if (BN) {
                        v0 = (v0 - rm[gc]) * rsqrtf(rv[gc] + FEPS) * gamma[gc] + beta[gc];
                        v1 = (v1 - rm[gc + 1]) * rsqrtf(rv[gc + 1] + FEPS) * gamma[gc + 1] + beta[gc + 1];
                        v0 = fmaxf(v0, 0.0f);
                        v1 = fmaxf(v1, 0.0f);
                    }
                    C1[row * NOUT + gc] = v0;
                    C1[row * NOUT + gc + 1] = v1;
                }
            }
        }
    }
#undef LOAD_ITER
#undef STORE_ITER
#undef COMPUTE
}

// ---------------- launch ----------------------------------------------------
extern "C" void kernel_launch(void* const* d_in, const int* in_sizes, int n_in,
                              void* d_out, int out_size) {
    const float* x    = (const float*)d_in[0];
    const void*  eidx = d_in[1];
    const float* W1l  = (const float*)d_in[2];
    const float* b1l  = (const float*)d_in[3];
    const float* W1r  = (const float*)d_in[4];
    const float* g1   = (const float*)d_in[5];
    const float* be1  = (const float*)d_in[6];
    const float* rm1  = (const float*)d_in[7];
    const float* rv1  = (const float*)d_in[8];
    const float* W2l  = (const float*)d_in[9];
    const float* b2l  = (const float*)d_in[10];
    const float* W2r  = (const float*)d_in[11];
    const float* g2   = (const float*)d_in[12];
    const float* be2  = (const float*)d_in[13];
    const float* rm2  = (const float*)d_in[14];
    const float* rv2  = (const float*)d_in[15];
    const float* Wcl  = (const float*)d_in[16];
    const float* bcl  = (const float*)d_in[17];
    const float* Wcr  = (const float*)d_in[18];
    float* out = (float*)d_out;

    int* p_degi;        cudaGetSymbolAddress((void**)&p_degi, g_degi);
    float* p_msg;       cudaGetSymbolAddress((void**)&p_msg, g_msg);
    float* p_h1;        cudaGetSymbolAddress((void**)&p_h1, g_h1);
    float* p_h2;        cudaGetSymbolAddress((void**)&p_h2, g_h2);
    float* p_t;         cudaGetSymbolAddress((void**)&p_t, g_t);
    float* p_r;         cudaGetSymbolAddress((void**)&p_r, g_r);
    __nv_bfloat16* wh;  cudaGetSymbolAddress((void**)&wh, g_wh);
    __nv_bfloat16* wl;  cudaGetSymbolAddress((void**)&wl, g_wl);

    const int DSMEM = 2 * BUFB;  // 61440
    cudaFuncSetAttribute(k_mgemm<INC, HIDC, 2, true, true, false>,
                         cudaFuncAttributeMaxDynamicSharedMemorySize, DSMEM);
    cudaFuncSetAttribute(k_mgemm<HIDC, HIDC, 2, true, true, false>,
                         cudaFuncAttributeMaxDynamicSharedMemorySize, DSMEM);
    cudaFuncSetAttribute(k_mgemm<HIDC, 128, 1, true, false, true>,
                         cudaFuncAttributeMaxDynamicSharedMemorySize, DSMEM);

    // 0) CSR build
    k_zero_detect<<<NBLK1, 256>>>(p_degi, NN, (const int*)eidx);
    k_degi<<<(EE + 255) / 256, 256>>>(eidx);
    k_scan1<<<NBLK1, 256>>>();
    k_scan2<<<1, 512>>>();
    k_scan3<<<NBLK1, 256>>>();
    k_fill<<<(EE + 255) / 256, 256>>>(eidx);

    // 1) weight transpose + split
    k_wsplit<<<(INC * HIDC + 255) / 256, 256>>>(W1l, wh + WO_1L, wl + WO_1L, INC, HIDC);
    k_wsplit<<<(INC * HIDC + 255) / 256, 256>>>(W1r, wh + WO_1R, wl + WO_1R, INC, HIDC);
    k_wsplit<<<(HIDC * HIDC + 255) / 256, 256>>>(W2l, wh + WO_2L, wl + WO_2L, HIDC, HIDC);
    k_wsplit<<<(HIDC * HIDC + 255) / 256, 256>>>(W2r, wh + WO_2R, wl + WO_2R, HIDC, HIDC);
    k_wsplit<<<(HIDC * OUTC + 255) / 256, 256>>>(Wcl, wh + WO_CL, wl + WO_CL, HIDC, OUTC);
    k_wsplit<<<(HIDC * OUTC + 255) / 256, 256>>>(Wcr, wh + WO_CR, wl + WO_CR, HIDC, OUTC);

    const int MBLK = (NN + 127) / 128;  // 782

    // 2) layer 1: agg (1 warp/node, CH=4) -> GEMM(+BN+ReLU)
    k_agg<4, 1, false><<<(NN + 7) / 8, 256>>>(x, nullptr, p_msg);
    k_mgemm<INC, HIDC, 2, true, true, false><<<dim3(MBLK, HIDC / 64), 256, DSMEM>>>(
        p_msg, x, wh + WO_1L, wl + WO_1L, wh + WO_1R, wl + WO_1R,
        b1l, g1, be1, rm1, rv1, p_h1, nullptr);

    // 3) layer 2: agg (2 warps/node, CH=4) -> GEMM(+BN+ReLU)
    k_agg<4, 2, false><<<(NN * 2 + 7) / 8, 256>>>(p_h1, nullptr, p_msg);
    k_mgemm<HIDC, HIDC, 2, true, true, false><<<dim3(MBLK, HIDC / 64), 256, DSMEM>>>(
        p_msg, p_h1, wh + WO_2L, wl + WO_2L, wh + WO_2R, wl + WO_2R,
        b2l, g2, be2, rm2, rv2, p_h2, nullptr);

    // 4) layer 3: dual GEMM (t = h2@Wcl, r = h2@Wcr + bcl), then out = agg(t)+r
    k_mgemm<HIDC, 128, 1, true, false, true><<<dim3(MBLK, 2), 256, DSMEM>>>(
        p_h2, nullptr, wh + WO_CL, wl + WO_CL, nullptr, nullptr,
        bcl, nullptr, nullptr, nullptr, nullptr, p_t, p_r);
    k_agg<2, 1, true><<<(NN + 7) / 8, 256>>>(p_t, p_r, out);
}

// round 9
// speedup vs baseline: 1.1921x; 1.0874x over previous
#include <cuda_runtime.h>
#include <cuda_bf16.h>
#include <cuda_fp16.h>
#include <cstdint>

#define NN 100000
#define EE 1600000
#define INC 128
#define HIDC 256
#define OUTC 64
#define FEPS 1e-5f
#define NBLK1 ((NN + 255) / 256)

// ---------------- scratch ----------------------------------------------------
__device__ int   g_is64;
__device__ int   g_degi[NN];
__device__ int   g_incl[NN];
__device__ int   g_bsum[512];
__device__ int   g_boff[512];
__device__ int   g_rowptr[NN];
__device__ int   g_cursor[NN];
__device__ int   g_csrc[EE];
__device__ float g_msg[(size_t)NN * HIDC];
__device__ float g_h1[(size_t)NN * HIDC];
__device__ float g_h2[(size_t)NN * HIDC];
__device__ float g_r[(size_t)NN * OUTC];
// fp16 gather tables
__device__ __half g_xh[(size_t)NN * INC];
__device__ __half g_h1h[(size_t)NN * HIDC];
__device__ __half g_th[(size_t)NN * OUTC];
// transposed, split weights, [N][K] layout.
#define WO_1L 0
#define WO_1R 32768
#define WO_2L 65536
#define WO_2R 131072
#define WO_CL 196608
#define WO_CR 212992
__device__ __nv_bfloat16 g_wh[229376];
__device__ __nv_bfloat16 g_wl[229376];

// ---------------- PTX helpers ------------------------------------------------
__device__ __forceinline__ uint32_t smem_u32(const void* p) {
    uint32_t a;
    asm("{ .reg .u64 t; cvta.to.shared.u64 t, %1; cvt.u32.u64 %0, t; }"
        : "=r"(a) : "l"(p));
    return a;
}
#define LDSM4(r, addr)                                                          \
    asm volatile("ldmatrix.sync.aligned.m8n8.x4.shared.b16 {%0,%1,%2,%3}, [%4];"\
                 : "=r"((r)[0]), "=r"((r)[1]), "=r"((r)[2]), "=r"((r)[3])       \
                 : "r"(addr))
#define LDSM2(r, addr)                                                          \
    asm volatile("ldmatrix.sync.aligned.m8n8.x2.shared.b16 {%0,%1}, [%2];"      \
                 : "=r"((r)[0]), "=r"((r)[1]) : "r"(addr))
#define MMA16816(d, a, b)                                                       \
    asm volatile("mma.sync.aligned.m16n8k16.row.col.f32.bf16.bf16.f32 "         \
                 "{%0,%1,%2,%3}, {%4,%5,%6,%7}, {%8,%9}, {%0,%1,%2,%3};"        \
                 : "+f"((d)[0]), "+f"((d)[1]), "+f"((d)[2]), "+f"((d)[3])       \
                 : "r"((a)[0]), "r"((a)[1]), "r"((a)[2]), "r"((a)[3]),          \
                   "r"((b)[0]), "r"((b)[1]))

// ---------------- misc kernels ----------------------------------------------
__device__ __forceinline__ int load_idx(const void* base, long long i) {
    if (g_is64) return (int)((const long long*)base)[i];
    return ((const int*)base)[i];
}
__global__ void k_zero_detect(int* p, int n, const int* e32) {
    int i = blockIdx.x * blockDim.x + threadIdx.x;
    if (i < n) p[i] = 0;
    if (blockIdx.x == 0 && threadIdx.x == 0) {
        int is64 = 1;
        for (int q = 0; q < 32; q++)
            if (e32[2 * q + 1] != 0) is64 = 0;
        g_is64 = is64;
    }
}
__global__ void k_degi(const void* eidx) {
    int e = blockIdx.x * blockDim.x + threadIdx.x;
    if (e < EE) atomicAdd(&g_degi[load_idx(eidx, (long long)EE + e)], 1);
}
__global__ void k_scan1() {
    __shared__ int s[256];
    int i = blockIdx.x * 256 + threadIdx.x;
    int v = (i < NN) ? g_degi[i] : 0;
    s[threadIdx.x] = v;
    __syncthreads();
#pragma unroll
    for (int off = 1; off < 256; off <<= 1) {
        int t = (threadIdx.x >= off) ? s[threadIdx.x - off] : 0;
        __syncthreads();
        s[threadIdx.x] += t;
        __syncthreads();
    }
    if (i < NN) g_incl[i] = s[threadIdx.x];
    if (threadIdx.x == 255) g_bsum[blockIdx.x] = s[255];
}
__global__ void k_scan2() {
    __shared__ int s[512];
    int tid = threadIdx.x;
    s[tid] = (tid < NBLK1) ? g_bsum[tid] : 0;
    __syncthreads();
#pragma unroll
    for (int off = 1; off < 512; off <<= 1) {
        int t = (tid >= off) ? s[tid - off] : 0;
        __syncthreads();
        s[tid] += t;
        __syncthreads();
    }
    g_boff[tid] = s[tid];
}
__global__ void k_scan3() {
    int i = blockIdx.x * 256 + threadIdx.x;
    if (i < NN) {
        int off = (blockIdx.x > 0) ? g_boff[blockIdx.x - 1] : 0;
        int start = off + g_incl[i] - g_degi[i];
        g_rowptr[i] = start;
        g_cursor[i] = start;
    }
}
__global__ void k_fill(const void* eidx) {
    int e = blockIdx.x * blockDim.x + threadIdx.x;
    if (e < EE) {
        int s = load_idx(eidx, e);
        int d = load_idx(eidx, (long long)EE + e);
        g_csrc[atomicAdd(&g_cursor[d], 1)] = s;
    }
}
// fp32 -> fp16 elementwise (vectorized via half2)
__global__ void k_tohalf(const float* __restrict__ in, __half* __restrict__ out,
                         long long n2) {
    long long i = (long long)blockIdx.x * blockDim.x + threadIdx.x;
    long long stride = (long long)gridDim.x * blockDim.x;
    const float2* in2 = (const float2*)in;
    __half2* out2 = (__half2*)out;
    for (; i < n2; i += stride) out2[i] = __float22half2_rn(in2[i]);
}

// ---------------- gather mean aggregation (fp16 tables, fp32 accum) ----------
template <int CH>
__device__ __forceinline__ void vloadh(float (&r)[CH], const __half* p) {
    uint32_t u[CH / 2];
    if (CH == 2) {
        u[0] = *(const uint32_t*)p;
    } else if (CH == 4) {
        uint2 v = *(const uint2*)p;
        u[0] = v.x; u[1] = v.y;
    } else {
        uint4 v = *(const uint4*)p;
        u[0] = v.x; u[1] = v.y; u[2] = v.z; u[3] = v.w;
    }
#pragma unroll
    for (int q = 0; q < CH / 2; q++) {
        __half2 h = *(__half2*)&u[q];
        float2 f = __half22float2(h);
        r[2 * q + 0] = f.x;
        r[2 * q + 1] = f.y;
    }
}
template <int CH>
__device__ __forceinline__ void vload(float (&r)[CH], const float* p) {
    if (CH == 2) {
        float2 v = *(const float2*)p;
        r[0] = v.x; r[1] = v.y;
    } else {
#pragma unroll
        for (int q = 0; q < CH / 4; q++) {
            float4 v = *(const float4*)(p + q * 4);
            r[q * 4 + 0] = v.x; r[q * 4 + 1] = v.y;
            r[q * 4 + 2] = v.z; r[q * 4 + 3] = v.w;
        }
    }
}
template <int CH>
__device__ __forceinline__ void vstore(float* p, const float (&r)[CH]) {
    if (CH == 2) {
        *(float2*)p = make_float2(r[0], r[1]);
    } else {
#pragma unroll
        for (int q = 0; q < CH / 4; q++)
            *(float4*)(p + q * 4) =
                make_float4(r[q * 4 + 0], r[q * 4 + 1], r[q * 4 + 2], r[q * 4 + 3]);
    }
}

template <int CH, bool ADD_EXTRA>
__global__ void k_agg(const __half* __restrict__ feat,
                      const float* __restrict__ extra,
                      float* __restrict__ outp) {
    const int D = 32 * CH;
    int warp = (blockIdx.x * blockDim.x + threadIdx.x) >> 5;
    int lane = threadIdx.x & 31;
    if (warp >= NN) return;
    int start = g_rowptr[warp];
    int dg = g_degi[warp];
    const __half* fb = feat + lane * CH;

    float acc[CH];
#pragma unroll
    for (int v = 0; v < CH; v++) acc[v] = 0.0f;

    int j = 0;
    for (; j + 4 <= dg; j += 4) {
        int s0 = g_csrc[start + j + 0];
        int s1 = g_csrc[start + j + 1];
        int s2 = g_csrc[start + j + 2];
        int s3 = g_csrc[start + j + 3];
        float r0[CH], r1[CH], r2[CH], r3[CH];
        vloadh<CH>(r0, fb + (long long)s0 * D);
        vloadh<CH>(r1, fb + (long long)s1 * D);
        vloadh<CH>(r2, fb + (long long)s2 * D);
        vloadh<CH>(r3, fb + (long long)s3 * D);
#pragma unroll
        for (int v = 0; v < CH; v++) acc[v] += r0[v];
#pragma unroll
        for (int v = 0; v < CH; v++) acc[v] += r1[v];
#pragma unroll
        for (int v = 0; v < CH; v++) acc[v] += r2[v];
#pragma unroll
        for (int v = 0; v < CH; v++) acc[v] += r3[v];
    }
    for (; j < dg; j++) {
        int s0 = g_csrc[start + j];
        float r0[CH];
        vloadh<CH>(r0, fb + (long long)s0 * D);
#pragma unroll
        for (int v = 0; v < CH; v++) acc[v] += r0[v];
    }

    float inv = (dg > 0) ? (1.0f / (float)dg) : 0.0f;
    float* op = outp + (long long)warp * D + lane * CH;
#pragma unroll
    for (int v = 0; v < CH; v++) acc[v] *= inv;
    if (ADD_EXTRA) {
        float ex[CH];
        vload<CH>(ex, extra + (long long)warp * D + lane * CH);
#pragma unroll
        for (int v = 0; v < CH; v++) acc[v] += ex[v];
    }
    vstore<CH>(op, acc);
}

// W[K,N] fp32 -> Wt[N,K] bf16 hi/lo
__global__ void k_wsplit(const float* __restrict__ W,
                         __nv_bfloat16* __restrict__ th,
                         __nv_bfloat16* __restrict__ tl, int K, int N) {
    int i = blockIdx.x * blockDim.x + threadIdx.x;
    if (i < K * N) {
        int k = i / N, n = i % N;
        float v = W[i];
        __nv_bfloat16 h = __float2bfloat16(v);
        th[n * K + k] = h;
        tl[n * K + k] = __float2bfloat16(v - __bfloat162float(h));
    }
}

// ---------------- mma.sync bf16-split GEMM, BM=128 BN=64, double-buffered ----
// WH: also write fp16 copy of C1 (gather table).
// DUAL: cols [0,64) -> fp16 table Th; cols [64,128) -> fp32 C2 (+bias).
#define ASTR 40
#define OAH 0
#define OAL 10240
#define OBH 20480
#define OBL 25600
#define BUFB 30720
template <int KTOT, int NOUT, int NMAT, bool HAS_BIAS, bool BN, bool DUAL, bool WH>
__global__ void __launch_bounds__(256) k_mgemm(
    const float* __restrict__ A1, const float* __restrict__ A2,
    const __nv_bfloat16* __restrict__ B1h, const __nv_bfloat16* __restrict__ B1l,
    const __nv_bfloat16* __restrict__ B2h, const __nv_bfloat16* __restrict__ B2l,
    const float* __restrict__ bias, const float* __restrict__ gamma,
    const float* __restrict__ beta, const float* __restrict__ rm,
    const float* __restrict__ rv, float* __restrict__ C1,
    float* __restrict__ C2, __half* __restrict__ Th) {
    extern __shared__ __align__(16) char dsm[];

    const int tid = threadIdx.x;
    const int lane = tid & 31;
    const int wid = tid >> 5;
    const int wm = wid & 3;
    const int wn = wid >> 2;
    const long long bm = (long long)blockIdx.x * 128;
    const int bn = blockIdx.y * 64;
    const int KC = KTOT / 32;
    const int TOT = NMAT * KC;

    float acc[2][4][4];
#pragma unroll
    for (int i = 0; i < 2; i++)
#pragma unroll
        for (int j = 0; j < 4; j++)
#pragma unroll
            for (int q = 0; q < 4; q++) acc[i][j][q] = 0.0f;

    const uint32_t sb = smem_u32(dsm);
    const uint32_t loA = (((wm * 32 + (lane & 15)) * ASTR + ((lane >> 4) << 3)) << 1);
    const uint32_t loB = (((wn * 32 + (lane & 7)) * ASTR + (((lane >> 3) & 1) << 3)) << 1);

    float4 aR[4];
    uint4 bhR, blR;

#define LOAD_ITER(it) do {                                                       \
    int _m = (it) / KC, _kc = (it) % KC, _k0 = _kc * 32;                         \
    const float* _A = (_m == 0) ? A1 : A2;                                       \
    const __nv_bfloat16* _Bh = (_m == 0) ? B1h : B2h;                            \
    const __nv_bfloat16* _Bl = (_m == 0) ? B1l : B2l;                            \
    _Pragma("unroll")                                                            \
    for (int _i = 0; _i < 4; _i++) {                                             \
        int _s = tid + _i * 256;                                                 \
        int _r = _s >> 3, _c = _s & 7;                                           \
        long long _grow = bm + _r;                                               \
        float4 _v = make_float4(0.f, 0.f, 0.f, 0.f);                             \
        if (_grow < NN) _v = *(const float4*)(_A + _grow * KTOT + _k0 + _c * 4); \
        aR[_i] = _v;                                                             \
    }                                                                            \
    {                                                                            \
        int _r = tid >> 2, _c = tid & 3;                                         \
        long long _off = (long long)(bn + _r) * KTOT + _k0 + _c * 8;             \
        bhR = *(const uint4*)(_Bh + _off);                                       \
        blR = *(const uint4*)(_Bl + _off);                                       \
    }                                                                            \
} while (0)

#define STORE_ITER(buf) do {                                                     \
    char* _S = dsm + (buf) * BUFB;                                               \
    _Pragma("unroll")                                                            \
    for (int _i = 0; _i < 4; _i++) {                                             \
        int _s = tid + _i * 256;                                                 \
        int _r = _s >> 3, _c = _s & 7;                                           \
        float _f[4] = {aR[_i].x, aR[_i].y, aR[_i].z, aR[_i].w};                  \
        uint32_t _h01, _h23, _l01, _l23;                                         \
        {                                                                        \
            __nv_bfloat16 _h0 = __float2bfloat16(_f[0]);                         \
            __nv_bfloat16 _h1 = __float2bfloat16(_f[1]);                         \
            __nv_bfloat16 _h2 = __float2bfloat16(_f[2]);                         \
            __nv_bfloat16 _h3 = __float2bfloat16(_f[3]);                         \
            __nv_bfloat16 _l0 = __float2bfloat16(_f[0] - __bfloat162float(_h0)); \
            __nv_bfloat16 _l1 = __float2bfloat16(_f[1] - __bfloat162float(_h1)); \
            __nv_bfloat16 _l2 = __float2bfloat16(_f[2] - __bfloat162float(_h2)); \
            __nv_bfloat16 _l3 = __float2bfloat16(_f[3] - __bfloat162float(_h3)); \
            _h01 = ((uint32_t)__bfloat16_as_ushort(_h1) << 16) |                 \
                   __bfloat16_as_ushort(_h0);                                    \
            _h23 = ((uint32_t)__bfloat16_as_ushort(_h3) << 16) |                 \
                   __bfloat16_as_ushort(_h2);                                    \
            _l01 = ((uint32_t)__bfloat16_as_ushort(_l1) << 16) |                 \
                   __bfloat16_as_ushort(_l0);                                    \
            _l23 = ((uint32_t)__bfloat16_as_ushort(_l3) << 16) |                 \
                   __bfloat16_as_ushort(_l2);                                    \
        }                                                                        \
        *(uint2*)(_S + OAH + (_r * ASTR + _c * 4) * 2) = make_uint2(_h01, _h23); \
        *(uint2*)(_S + OAL + (_r * ASTR + _c * 4) * 2) = make_uint2(_l01, _l23); \
    }                                                                            \
    {                                                                            \
        int _r = tid >> 2, _c = tid & 3;                                         \
        *(uint4*)(_S + OBH + (_r * ASTR + _c * 8) * 2) = bhR;                    \
        *(uint4*)(_S + OBL + (_r * ASTR + _c * 8) * 2) = blR;                    \
    }                                                                            \
} while (0)

#define COMPUTE(buf) do {                                                        \
    const uint32_t _b = sb + (buf) * BUFB;                                       \
    const uint32_t _aAh = _b + OAH + loA;                                        \
    const uint32_t _aAl = _b + OAL + loA;                                        \
    const uint32_t _aBh = _b + OBH + loB;                                        \
    const uint32_t _aBl = _b + OBL + loB;                                        \
    _Pragma("unroll")                                                            \
    for (int _ka = 0; _ka < 2; _ka++) {                                          \
        const uint32_t _ko = _ka * 32;                                           \
        uint32_t _ah[2][4], _al[2][4], _bh[4][2], _bl[4][2];                     \
        LDSM4(_ah[0], _aAh + _ko);                                               \
        LDSM4(_ah[1], _aAh + 1280 + _ko);                                        \
        LDSM4(_al[0], _aAl + _ko);                                               \
        LDSM4(_al[1], _aAl + 1280 + _ko);                                        \
        _Pragma("unroll")                                                        \
        for (int _na = 0; _na < 4; _na++) {                                      \
            LDSM2(_bh[_na], _aBh + _na * 640 + _ko);                             \
            LDSM2(_bl[_na], _aBl + _na * 640 + _ko);                             \
        }                                                                        \
        _Pragma("unroll")                                                        \
        for (int _ma = 0; _ma < 2; _ma++)                                        \
            _Pragma("unroll")                                                    \
            for (int _na = 0; _na < 4; _na++) {                                  \
                MMA16816(acc[_ma][_na], _ah[_ma], _bh[_na]);                     \
                MMA16816(acc[_ma][_na], _ah[_ma], _bl[_na]);                     \
                MMA16816(acc[_ma][_na], _al[_ma], _bh[_na]);                     \
            }                                                                    \
    }                                                                            \
} while (0)

    LOAD_ITER(0);
    STORE_ITER(0);
    __syncthreads();
    for (int it = 0; it < TOT; it++) {
        const int cur = it & 1;
        if (it + 1 < TOT) LOAD_ITER(it + 1);
        COMPUTE(cur);
        if (it + 1 < TOT) STORE_ITER(cur ^ 1);
        __syncthreads();
    }

    const int g = lane >> 2, t = lane & 3;
#pragma unroll
    for (int ma = 0; ma < 2; ma++) {
#pragma unroll
        for (int na = 0; na < 4; na++) {
            int lcol = wn * 32 + na * 8 + 2 * t;
            int gc = bn + lcol;
#pragma unroll
            for (int half = 0; half < 2; half++) {
                long long row = bm + wm * 32 + ma * 16 + g + half * 8;
                if (row >= NN) continue;
                float v0 = acc[ma][na][half * 2 + 0];
                float v1 = acc[ma][na][half * 2 + 1];
                if (DUAL) {
                    if (gc < 64) {
                        // t table: fp16 only (consumed by gather)
                        *(__half2*)&Th[row * 64 + gc] = __floats2half2_rn(v0, v1);
                    } else {
                        C2[row * 64 + gc - 64] = v0 + bias[gc - 64];
                        C2[row * 64 + gc - 63] = v1 + bias[gc - 63];
                    }
                } else {
                    if (HAS_BIAS) { v0 += bias[gc]; v1 += bias[gc + 1]; }
                    if (BN) {
                        v0 = (v0 - rm[gc]) * rsqrtf(rv[gc] + FEPS) * gamma[gc] + beta[gc];
                        v1 = (v1 - rm[gc + 1]) * rsqrtf(rv[gc + 1] + FEPS) * gamma[gc + 1] + beta[gc + 1];
                        v0 = fmaxf(v0, 0.0f);
                        v1 = fmaxf(v1, 0.0f);
                    }
                    C1[row * NOUT + gc] = v0;
                    C1[row * NOUT + gc + 1] = v1;
                    if (WH)
                        *(__half2*)&Th[row * NOUT + gc] = __floats2half2_rn(v0, v1);
                }
            }
        }
    }
#undef LOAD_ITER
#undef STORE_ITER
#undef COMPUTE
}

// ---------------- launch ----------------------------------------------------
extern "C" void kernel_launch(void* const* d_in, const int* in_sizes, int n_in,
                              void* d_out, int out_size) {
    const float* x    = (const float*)d_in[0];
    const void*  eidx = d_in[1];
    const float* W1l  = (const float*)d_in[2];
    const float* b1l  = (const float*)d_in[3];
    const float* W1r  = (const float*)d_in[4];
    const float* g1   = (const float*)d_in[5];
    const float* be1  = (const float*)d_in[6];
    const float* rm1  = (const float*)d_in[7];
    const float* rv1  = (const float*)d_in[8];
    const float* W2l  = (const float*)d_in[9];
    const float* b2l  = (const float*)d_in[10];
    const float* W2r  = (const float*)d_in[11];
    const float* g2   = (const float*)d_in[12];
    const float* be2  = (const float*)d_in[13];
    const float* rm2  = (const float*)d_in[14];
    const float* rv2  = (const float*)d_in[15];
    const float* Wcl  = (const float*)d_in[16];
    const float* bcl  = (const float*)d_in[17];
    const float* Wcr  = (const float*)d_in[18];
    float* out = (float*)d_out;

    int* p_degi;        cudaGetSymbolAddress((void**)&p_degi, g_degi);
    float* p_msg;       cudaGetSymbolAddress((void**)&p_msg, g_msg);
    float* p_h1;        cudaGetSymbolAddress((void**)&p_h1, g_h1);
    float* p_h2;        cudaGetSymbolAddress((void**)&p_h2, g_h2);
    float* p_r;         cudaGetSymbolAddress((void**)&p_r, g_r);
    __half* p_xh;       cudaGetSymbolAddress((void**)&p_xh, g_xh);
    __half* p_h1h;      cudaGetSymbolAddress((void**)&p_h1h, g_h1h);
    __half* p_th;       cudaGetSymbolAddress((void**)&p_th, g_th);
    __nv_bfloat16* wh;  cudaGetSymbolAddress((void**)&wh, g_wh);
    __nv_bfloat16* wl;  cudaGetSymbolAddress((void**)&wl, g_wl);

    const int DSMEM = 2 * BUFB;  // 61440
    cudaFuncSetAttribute(k_mgemm<INC, HIDC, 2, true, true, false, true>,
                         cudaFuncAttributeMaxDynamicSharedMemorySize, DSMEM);
    cudaFuncSetAttribute(k_mgemm<HIDC, HIDC, 2, true, true, false, false>,
                         cudaFuncAttributeMaxDynamicSharedMemorySize, DSMEM);
    cudaFuncSetAttribute(k_mgemm<HIDC, 128, 1, true, false, true, false>,
                         cudaFuncAttributeMaxDynamicSharedMemorySize, DSMEM);

    // 0) CSR build
    k_zero_detect<<<NBLK1, 256>>>(p_degi, NN, (const int*)eidx);
    k_degi<<<(EE + 255) / 256, 256>>>(eidx);
    k_scan1<<<NBLK1, 256>>>();
    k_scan2<<<1, 512>>>();
    k_scan3<<<NBLK1, 256>>>();
    k_fill<<<(EE + 255) / 256, 256>>>(eidx);

    // 1) weight transpose + split; x -> fp16 gather table
    k_wsplit<<<(INC * HIDC + 255) / 256, 256>>>(W1l, wh + WO_1L, wl + WO_1L, INC, HIDC);
    k_wsplit<<<(INC * HIDC + 255) / 256, 256>>>(W1r, wh + WO_1R, wl + WO_1R, INC, HIDC);
    k_wsplit<<<(HIDC * HIDC + 255) / 256, 256>>>(W2l, wh + WO_2L, wl + WO_2L, HIDC, HIDC);
    k_wsplit<<<(HIDC * HIDC + 255) / 256, 256>>>(W2r, wh + WO_2R, wl + WO_2R, HIDC, HIDC);
    k_wsplit<<<(HIDC * OUTC + 255) / 256, 256>>>(Wcl, wh + WO_CL, wl + WO_CL, HIDC, OUTC);
    k_wsplit<<<(HIDC * OUTC + 255) / 256, 256>>>(Wcr, wh + WO_CR, wl + WO_CR, HIDC, OUTC);
    k_tohalf<<<4096, 256>>>(x, p_xh, (long long)NN * INC / 2);

    const int MBLK = (NN + 127) / 128;  // 782
    const int AGG_BLOCKS = (NN + 7) / 8;

    // 2) layer 1: fp16 gather -> GEMM(+BN+ReLU); epilogue writes h1 fp32 + fp16
    k_agg<INC / 32, false><<<AGG_BLOCKS, 256>>>(p_xh, nullptr, p_msg);
    k_mgemm<INC, HIDC, 2, true, true, false, true><<<dim3(MBLK, HIDC / 64), 256, DSMEM>>>(
        p_msg, x, wh + WO_1L, wl + WO_1L, wh + WO_1R, wl + WO_1R,
        b1l, g1, be1, rm1, rv1, p_h1, nullptr, p_h1h);

    // 3) layer 2: fp16 gather of h1 -> GEMM(+BN+ReLU)
    k_agg<HIDC / 32, false><<<AGG_BLOCKS, 256>>>(p_h1h, nullptr, p_msg);
    k_mgemm<HIDC, HIDC, 2, true, true, false, false><<<dim3(MBLK, HIDC / 64), 256, DSMEM>>>(
        p_msg, p_h1, wh + WO_2L, wl + WO_2L, wh + WO_2R, wl + WO_2R,
        b2l, g2, be2, rm2, rv2, p_h2, nullptr, nullptr);

    // 4) layer 3: dual GEMM (t -> fp16 table, r = h2@Wcr + bcl fp32),
    //    then out = fp16-gather-mean(t) + r
    k_mgemm<HIDC, 128, 1, true, false, true, false><<<dim3(MBLK, 2), 256, DSMEM>>>(
        p_h2, nullptr, wh + WO_CL, wl + WO_CL, nullptr, nullptr,
        bcl, nullptr, nullptr, nullptr, nullptr, nullptr, p_r, p_th);
    k_agg<OUTC / 32, true><<<AGG_BLOCKS, 256>>>(p_th, p_r, out);
}

// round 10
// speedup vs baseline: 1.1952x; 1.0026x over previous
#include <cuda_runtime.h>
#include <cuda_bf16.h>
#include <cuda_fp16.h>
#include <cstdint>

#define NN 100000
#define EE 1600000
#define INC 128
#define HIDC 256
#define OUTC 64
#define FEPS 1e-5f
#define NBLK1 ((NN + 255) / 256)

// ---------------- scratch ----------------------------------------------------
__device__ int   g_is64;
__device__ int   g_degi[NN];
__device__ int   g_incl[NN];
__device__ int   g_bsum[512];
__device__ int   g_boff[512];
__device__ int   g_rowptr[NN];
__device__ int   g_cursor[NN];
__device__ int   g_csrc[EE];
__device__ float g_msg[(size_t)NN * HIDC];
__device__ float g_h1[(size_t)NN * HIDC];
__device__ float g_h2[(size_t)NN * HIDC];
__device__ float g_r[(size_t)NN * OUTC];
// fp16 gather tables
__device__ __half g_xh[(size_t)NN * INC];
__device__ __half g_h1h[(size_t)NN * HIDC];
__device__ __half g_th[(size_t)NN * OUTC];
// transposed, split weights, [N][K] layout.
#define WO_1L 0
#define WO_1R 32768
#define WO_2L 65536
#define WO_2R 131072
#define WO_CL 196608
#define WO_CR 212992
__device__ __nv_bfloat16 g_wh[229376];
__device__ __nv_bfloat16 g_wl[229376];

// ---------------- PTX helpers ------------------------------------------------
__device__ __forceinline__ uint32_t smem_u32(const void* p) {
    uint32_t a;
    asm("{ .reg .u64 t; cvta.to.shared.u64 t, %1; cvt.u32.u64 %0, t; }"
        : "=r"(a) : "l"(p));
    return a;
}
#define LDSM4(r, addr)                                                          \
    asm volatile("ldmatrix.sync.aligned.m8n8.x4.shared.b16 {%0,%1,%2,%3}, [%4];"\
                 : "=r"((r)[0]), "=r"((r)[1]), "=r"((r)[2]), "=r"((r)[3])       \
                 : "r"(addr))
#define LDSM2(r, addr)                                                          \
    asm volatile("ldmatrix.sync.aligned.m8n8.x2.shared.b16 {%0,%1}, [%2];"      \
                 : "=r"((r)[0]), "=r"((r)[1]) : "r"(addr))
#define MMA16816(d, a, b)                                                       \
    asm volatile("mma.sync.aligned.m16n8k16.row.col.f32.bf16.bf16.f32 "         \
                 "{%0,%1,%2,%3}, {%4,%5,%6,%7}, {%8,%9}, {%0,%1,%2,%3};"        \
                 : "+f"((d)[0]), "+f"((d)[1]), "+f"((d)[2]), "+f"((d)[3])       \
                 : "r"((a)[0]), "r"((a)[1]), "r"((a)[2]), "r"((a)[3]),          \
                   "r"((b)[0]), "r"((b)[1]))

// ---------------- misc kernels ----------------------------------------------
__device__ __forceinline__ int load_idx(const void* base, long long i) {
    if (g_is64) return (int)((const long long*)base)[i];
    return ((const int*)base)[i];
}
__global__ void k_zero_detect(int* p, int n, const int* e32) {
    int i = blockIdx.x * blockDim.x + threadIdx.x;
    if (i < n) p[i] = 0;
    if (blockIdx.x == 0 && threadIdx.x == 0) {
        int is64 = 1;
        for (int q = 0; q < 32; q++)
            if (e32[2 * q + 1] != 0) is64 = 0;
        g_is64 = is64;
    }
}
__global__ void k_degi(const void* eidx) {
    int e = blockIdx.x * blockDim.x + threadIdx.x;
    if (e < EE) atomicAdd(&g_degi[load_idx(eidx, (long long)EE + e)], 1);
}
__global__ void k_scan1() {
    __shared__ int s[256];
    int i = blockIdx.x * 256 + threadIdx.x;
    int v = (i < NN) ? g_degi[i] : 0;
    s[threadIdx.x] = v;
    __syncthreads();
#pragma unroll
    for (int off = 1; off < 256; off <<= 1) {
        int t = (threadIdx.x >= off) ? s[threadIdx.x - off] : 0;
        __syncthreads();
        s[threadIdx.x] += t;
        __syncthreads();
    }
    if (i < NN) g_incl[i] = s[threadIdx.x];
    if (threadIdx.x == 255) g_bsum[blockIdx.x] = s[255];
}
__global__ void k_scan2() {
    __shared__ int s[512];
    int tid = threadIdx.x;
    s[tid] = (tid < NBLK1) ? g_bsum[tid] : 0;
    __syncthreads();
#pragma unroll
    for (int off = 1; off < 512; off <<= 1) {
        int t = (tid >= off) ? s[tid - off] : 0;
        __syncthreads();
        s[tid] += t;
        __syncthreads();
    }
    g_boff[tid] = s[tid];
}
__global__ void k_scan3() {
    int i = blockIdx.x * 256 + threadIdx.x;
    if (i < NN) {
        int off = (blockIdx.x > 0) ? g_boff[blockIdx.x - 1] : 0;
        int start = off + g_incl[i] - g_degi[i];
        g_rowptr[i] = start;
        g_cursor[i] = start;
    }
}
__global__ void k_fill(const void* eidx) {
    int e = blockIdx.x * blockDim.x + threadIdx.x;
    if (e < EE) {
        int s = load_idx(eidx, e);
        int d = load_idx(eidx, (long long)EE + e);
        g_csrc[atomicAdd(&g_cursor[d], 1)] = s;
    }
}
// fp32 -> fp16 elementwise (vectorized via half2)
__global__ void k_tohalf(const float* __restrict__ in, __half* __restrict__ out,
                         long long n2) {
    long long i = (long long)blockIdx.x * blockDim.x + threadIdx.x;
    long long stride = (long long)gridDim.x * blockDim.x;
    const float2* in2 = (const float2*)in;
    __half2* out2 = (__half2*)out;
    for (; i < n2; i += stride) out2[i] = __float22half2_rn(in2[i]);
}

// ---------------- gather mean aggregation (fp16 tables, fp32 accum) ----------
template <int CH>
__device__ __forceinline__ void vloadh(float (&r)[CH], const __half* p) {
    uint32_t u[CH / 2];
    if (CH == 2) {
        u[0] = *(const uint32_t*)p;
    } else if (CH == 4) {
        uint2 v = *(const uint2*)p;
        u[0] = v.x; u[1] = v.y;
    } else {
        uint4 v = *(const uint4*)p;
        u[0] = v.x; u[1] = v.y; u[2] = v.z; u[3] = v.w;
    }
#pragma unroll
    for (int q = 0; q < CH / 2; q++) {
        __half2 h = *(__half2*)&u[q];
        float2 f = __half22float2(h);
        r[2 * q + 0] = f.x;
        r[2 * q + 1] = f.y;
    }
}
template <int CH>
__device__ __forceinline__ void vload(float (&r)[CH], const float* p) {
    if (CH == 2) {
        float2 v = *(const float2*)p;
        r[0] = v.x; r[1] = v.y;
    } else {
#pragma unroll
        for (int q = 0; q < CH / 4; q++) {
            float4 v = *(const float4*)(p + q * 4);
            r[q * 4 + 0] = v.x; r[q * 4 + 1] = v.y;
            r[q * 4 + 2] = v.z; r[q * 4 + 3] = v.w;
        }
    }
}
template <int CH>
__device__ __forceinline__ void vstore(float* p, const float (&r)[CH]) {
    if (CH == 2) {
        *(float2*)p = make_float2(r[0], r[1]);
    } else {
#pragma unroll
        for (int q = 0; q < CH / 4; q++)
            *(float4*)(p + q * 4) =
                make_float4(r[q * 4 + 0], r[q * 4 + 1], r[q * 4 + 2], r[q * 4 + 3]);
    }
}

template <int CH, bool ADD_EXTRA>
__global__ void k_agg(const __half* __restrict__ feat,
                      const float* __restrict__ extra,
                      float* __restrict__ outp) {
    const int D = 32 * CH;
    int warp = (blockIdx.x * blockDim.x + threadIdx.x) >> 5;
    int lane = threadIdx.x & 31;
    if (warp >= NN) return;
    int start = g_rowptr[warp];
    int dg = g_degi[warp];
    const __half* fb = feat + lane * CH;

    float acc[CH];
#pragma unroll
    for (int v = 0; v < CH; v++) acc[v] = 0.0f;

    int j = 0;
    for (; j + 4 <= dg; j += 4) {
        int s0 = g_csrc[start + j + 0];
        int s1 = g_csrc[start + j + 1];
        int s2 = g_csrc[start + j + 2];
        int s3 = g_csrc[start + j + 3];
        float r0[CH], r1[CH], r2[CH], r3[CH];
        vloadh<CH>(r0, fb + (long long)s0 * D);
        vloadh<CH>(r1, fb + (long long)s1 * D);
        vloadh<CH>(r2, fb + (long long)s2 * D);
        vloadh<CH>(r3, fb + (long long)s3 * D);
#pragma unroll
        for (int v = 0; v < CH; v++) acc[v] += r0[v];
#pragma unroll
        for (int v = 0; v < CH; v++) acc[v] += r1[v];
#pragma unroll
        for (int v = 0; v < CH; v++) acc[v] += r2[v];
#pragma unroll
        for (int v = 0; v < CH; v++) acc[v] += r3[v];
    }
    for (; j < dg; j++) {
        int s0 = g_csrc[start + j];
        float r0[CH];
        vloadh<CH>(r0, fb + (long long)s0 * D);
#pragma unroll
        for (int v = 0; v < CH; v++) acc[v] += r0[v];
    }

    float inv = (dg > 0) ? (1.0f / (float)dg) : 0.0f;
    float* op = outp + (long long)warp * D + lane * CH;
#pragma unroll
    for (int v = 0; v < CH; v++) acc[v] *= inv;
    if (ADD_EXTRA) {
        float ex[CH];
        vload<CH>(ex, extra + (long long)warp * D + lane * CH);
#pragma unroll
        for (int v = 0; v < CH; v++) acc[v] += ex[v];
    }
    vstore<CH>(op, acc);
}

// W[K,N] fp32 -> Wt[N,K] bf16 hi/lo
__global__ void k_wsplit(const float* __restrict__ W,
                         __nv_bfloat16* __restrict__ th,
                         __nv_bfloat16* __restrict__ tl, int K, int N) {
    int i = blockIdx.x * blockDim.x + threadIdx.x;
    if (i < K * N) {
        int k = i / N, n = i % N;
        float v = W[i];
        __nv_bfloat16 h = __float2bfloat16(v);
        th[n * K + k] = h;
        tl[n * K + k] = __float2bfloat16(v - __bfloat162float(h));
    }
}

// ---------------- mma.sync bf16-split GEMM, BM=128 BN=64, double-buffered ----
// Grid is TRANSPOSED: blockIdx.x = n-tile (fast), blockIdx.y = m-tile.
// N-slices of one A-tile are wave-adjacent -> A fetched once into L2.
// WH: also write fp16 copy of C1. DUAL: cols [0,64)->fp16 Th; [64,128)->C2+bias.
#define ASTR 40
#define OAH 0
#define OAL 10240
#define OBH 20480
#define OBL 25600
#define BUFB 30720
template <int KTOT, int NOUT, int NMAT, bool HAS_BIAS, bool BN, bool DUAL, bool WH>
__global__ void __launch_bounds__(256) k_mgemm(
    const float* __restrict__ A1, const float* __restrict__ A2,
    const __nv_bfloat16* __restrict__ B1h, const __nv_bfloat16* __restrict__ B1l,
    const __nv_bfloat16* __restrict__ B2h, const __nv_bfloat16* __restrict__ B2l,
    const float* __restrict__ bias, const float* __restrict__ gamma,
    const float* __restrict__ beta, const float* __restrict__ rm,
    const float* __restrict__ rv, float* __restrict__ C1,
    float* __restrict__ C2, __half* __restrict__ Th) {
    extern __shared__ __align__(16) char dsm[];

    const int tid = threadIdx.x;
    const int lane = tid & 31;
    const int wid = tid >> 5;
    const int wm = wid & 3;
    const int wn = wid >> 2;
    const long long bm = (long long)blockIdx.y * 128;  // m from y (slow)
    const int bn = blockIdx.x * 64;                    // n from x (fast)
    const int KC = KTOT / 32;
    const int TOT = NMAT * KC;

    float acc[2][4][4];
#pragma unroll
    for (int i = 0; i < 2; i++)
#pragma unroll
        for (int j = 0; j < 4; j++)
#pragma unroll
            for (int q = 0; q < 4; q++) acc[i][j][q] = 0.0f;

    const uint32_t sb = smem_u32(dsm);
    const uint32_t loA = (((wm * 32 + (lane & 15)) * ASTR + ((lane >> 4) << 3)) << 1);
    const uint32_t loB = (((wn * 32 + (lane & 7)) * ASTR + (((lane >> 3) & 1) << 3)) << 1);

    float4 aR[4];
    uint4 bhR, blR;

#define LOAD_ITER(it) do {                                                       \
    int _m = (it) / KC, _kc = (it) % KC, _k0 = _kc * 32;                         \
    const float* _A = (_m == 0) ? A1 : A2;                                       \
    const __nv_bfloat16* _Bh = (_m == 0) ? B1h : B2h;                            \
    const __nv_bfloat16* _Bl = (_m == 0) ? B1l : B2l;                            \
    _Pragma("unroll")                                                            \
    for (int _i = 0; _i < 4; _i++) {                                             \
        int _s = tid + _i * 256;                                                 \
        int _r = _s >> 3, _c = _s & 7;                                           \
        long long _grow = bm + _r;                                               \
        float4 _v = make_float4(0.f, 0.f, 0.f, 0.f);                             \
        if (_grow < NN) _v = *(const float4*)(_A + _grow * KTOT + _k0 + _c * 4); \
        aR[_i] = _v;                                                             \
    }                                                                            \
    {                                                                            \
        int _r = tid >> 2, _c = tid & 3;                                         \
        long long _off = (long long)(bn + _r) * KTOT + _k0 + _c * 8;             \
        bhR = *(const uint4*)(_Bh + _off);                                       \
        blR = *(const uint4*)(_Bl + _off);                                       \
    }                                                                            \
} while (0)

#define STORE_ITER(buf) do {                                                     \
    char* _S = dsm + (buf) * BUFB;                                               \
    _Pragma("unroll")                                                            \
    for (int _i = 0; _i < 4; _i++) {                                             \
        int _s = tid + _i * 256;                                                 \
        int _r = _s >> 3, _c = _s & 7;                                           \
        float _f[4] = {aR[_i].x, aR[_i].y, aR[_i].z, aR[_i].w};                  \
        uint32_t _h01, _h23, _l01, _l23;                                         \
        {                                                                        \
            __nv_bfloat16 _h0 = __float2bfloat16(_f[0]);                         \
            __nv_bfloat16 _h1 = __float2bfloat16(_f[1]);                         \
            __nv_bfloat16 _h2 = __float2bfloat16(_f[2]);                         \
            __nv_bfloat16 _h3 = __float2bfloat16(_f[3]);                         \
            __nv_bfloat16 _l0 = __float2bfloat16(_f[0] - __bfloat162float(_h0)); \
            __nv_bfloat16 _l1 = __float2bfloat16(_f[1] - __bfloat162float(_h1)); \
            __nv_bfloat16 _l2 = __float2bfloat16(_f[2] - __bfloat162float(_h2)); \
            __nv_bfloat16 _l3 = __float2bfloat16(_f[3] - __bfloat162float(_h3)); \
            _h01 = ((uint32_t)__bfloat16_as_ushort(_h1) << 16) |                 \
                   __bfloat16_as_ushort(_h0);                                    \
            _h23 = ((uint32_t)__bfloat16_as_ushort(_h3) << 16) |                 \
                   __bfloat16_as_ushort(_h2);                                    \
            _l01 = ((uint32_t)__bfloat16_as_ushort(_l1) << 16) |                 \
                   __bfloat16_as_ushort(_l0);                                    \
            _l23 = ((uint32_t)__bfloat16_as_ushort(_l3) << 16) |                 \
                   __bfloat16_as_ushort(_l2);                                    \
        }                                                                        \
        *(uint2*)(_S + OAH + (_r * ASTR + _c * 4) * 2) = make_uint2(_h01, _h23); \
        *(uint2*)(_S + OAL + (_r * ASTR + _c * 4) * 2) = make_uint2(_l01, _l23); \
    }                                                                            \
    {                                                                            \
        int _r = tid >> 2, _c = tid & 3;                                         \
        *(uint4*)(_S + OBH + (_r * ASTR + _c * 8) * 2) = bhR;                    \
        *(uint4*)(_S + OBL + (_r * ASTR + _c * 8) * 2) = blR;                    \
    }                                                                            \
} while (0)

#define COMPUTE(buf) do {                                                        \
    const uint32_t _b = sb + (buf) * BUFB;                                       \
    const uint32_t _aAh = _b + OAH + loA;                                        \
    const uint32_t _aAl = _b + OAL + loA;                                        \
    const uint32_t _aBh = _b + OBH + loB;                                        \
    const uint32_t _aBl = _b + OBL + loB;                                        \
    _Pragma("unroll")                                                            \
    for (int _ka = 0; _ka < 2; _ka++) {                                          \
        const uint32_t _ko = _ka * 32;                                           \
        uint32_t _ah[2][4], _al[2][4], _bh[4][2], _bl[4][2];                     \
        LDSM4(_ah[0], _aAh + _ko);                                               \
        LDSM4(_ah[1], _aAh + 1280 + _ko);                                        \
        LDSM4(_al[0], _aAl + _ko);                                               \
        LDSM4(_al[1], _aAl + 1280 + _ko);                                        \
        _Pragma("unroll")                                                        \
        for (int _na = 0; _na < 4; _na++) {                                      \
            LDSM2(_bh[_na], _aBh + _na * 640 + _ko);                             \
            LDSM2(_bl[_na], _aBl + _na * 640 + _ko);                             \
        }                                                                        \
        _Pragma("unroll")                                                        \
        for (int _ma = 0; _ma < 2; _ma++)                                        \
            _Pragma("unroll")                                                    \
            for (int _na = 0; _na < 4; _na++) {                                  \
                MMA16816(acc[_ma][_na], _ah[_ma], _bh[_na]);                     \
                MMA16816(acc[_ma][_na], _ah[_ma], _bl[_na]);                     \
                MMA16816(acc[_ma][_na], _al[_ma], _bh[_na]);                     \
            }                                                                    \
    }                                                                            \
} while (0)

    LOAD_ITER(0);
    STORE_ITER(0);
    __syncthreads();
    for (int it = 0; it < TOT; it++) {
        const int cur = it & 1;
        if (it + 1 < TOT) LOAD_ITER(it + 1);
        COMPUTE(cur);
        if (it + 1 < TOT) STORE_ITER(cur ^ 1);
        __syncthreads();
    }

    const int g = lane >> 2, t = lane & 3;
#pragma unroll
    for (int ma = 0; ma < 2; ma++) {
#pragma unroll
        for (int na = 0; na < 4; na++) {
            int lcol = wn * 32 + na * 8 + 2 * t;
            int gc = bn + lcol;
#pragma unroll
            for (int half = 0; half < 2; half++) {
                long long row = bm + wm * 32 + ma * 16 + g + half * 8;
                if (row >= NN) continue;
                float v0 = acc[ma][na][half * 2 + 0];
                float v1 = acc[ma][na][half * 2 + 1];
                if (DUAL) {
                    if (gc < 64) {
                        *(__half2*)&Th[row * 64 + gc] = __floats2half2_rn(v0, v1);
                    } else {
                        C2[row * 64 + gc - 64] = v0 + bias[gc - 64];
                        C2[row * 64 + gc - 63] = v1 + bias[gc - 63];
                    }
                } else {
                    if (HAS_BIAS) { v0 += bias[gc]; v1 += bias[gc + 1]; }
                    if (BN) {
                        v0 = (v0 - rm[gc]) * rsqrtf(rv[gc] + FEPS) * gamma[gc] + beta[gc];
                        v1 = (v1 - rm[gc + 1]) * rsqrtf(rv[gc + 1] + FEPS) * gamma[gc + 1] + beta[gc + 1];
                        v0 = fmaxf(v0, 0.0f);
                        v1 = fmaxf(v1, 0.0f);
                    }
                    C1[row * NOUT + gc] = v0;
                    C1[row * NOUT + gc + 1] = v1;
                    if (WH)
                        *(__half2*)&Th[row * NOUT + gc] = __floats2half2_rn(v0, v1);
                }
            }
        }
    }
#undef LOAD_ITER
#undef STORE_ITER
#undef COMPUTE
}

// ---------------- launch ----------------------------------------------------
extern "C" void kernel_launch(void* const* d_in, const int* in_sizes, int n_in,
                              void* d_out, int out_size) {
    const float* x    = (const float*)d_in[0];
    const void*  eidx = d_in[1];
    const float* W1l  = (const float*)d_in[2];
    const float* b1l  = (const float*)d_in[3];
    const float* W1r  = (const float*)d_in[4];
    const float* g1   = (const float*)d_in[5];
    const float* be1  = (const float*)d_in[6];
    const float* rm1  = (const float*)d_in[7];
    const float* rv1  = (const float*)d_in[8];
    const float* W2l  = (const float*)d_in[9];
    const float* b2l  = (const float*)d_in[10];
    const float* W2r  = (const float*)d_in[11];
    const float* g2   = (const float*)d_in[12];
    const float* be2  = (const float*)d_in[13];
    const float* rm2  = (const float*)d_in[14];
    const float* rv2  = (const float*)d_in[15];
    const float* Wcl  = (const float*)d_in[16];
    const float* bcl  = (const float*)d_in[17];
    const float* Wcr  = (const float*)d_in[18];
    float* out = (float*)d_out;

    int* p_degi;        cudaGetSymbolAddress((void**)&p_degi, g_degi);
    float* p_msg;       cudaGetSymbolAddress((void**)&p_msg, g_msg);
    float* p_h1;        cudaGetSymbolAddress((void**)&p_h1, g_h1);
    float* p_h2;        cudaGetSymbolAddress((void**)&p_h2, g_h2);
    float* p_r;         cudaGetSymbolAddress((void**)&p_r, g_r);
    __half* p_xh;       cudaGetSymbolAddress((void**)&p_xh, g_xh);
    __half* p_h1h;      cudaGetSymbolAddress((void**)&p_h1h, g_h1h);
    __half* p_th;       cudaGetSymbolAddress((void**)&p_th, g_th);
    __nv_bfloat16* wh;  cudaGetSymbolAddress((void**)&wh, g_wh);
    __nv_bfloat16* wl;  cudaGetSymbolAddress((void**)&wl, g_wl);

    const int DSMEM = 2 * BUFB;  // 61440
    cudaFuncSetAttribute(k_mgemm<INC, HIDC, 2, true, true, false, true>,
                         cudaFuncAttributeMaxDynamicSharedMemorySize, DSMEM);
    cudaFuncSetAttribute(k_mgemm<HIDC, HIDC, 2, true, true, false, false>,
                         cudaFuncAttributeMaxDynamicSharedMemorySize, DSMEM);
    cudaFuncSetAttribute(k_mgemm<HIDC, 128, 1, true, false, true, false>,
                         cudaFuncAttributeMaxDynamicSharedMemorySize, DSMEM);

    // 0) CSR build
    k_zero_detect<<<NBLK1, 256>>>(p_degi, NN, (const int*)eidx);
    k_degi<<<(EE + 255) / 256, 256>>>(eidx);
    k_scan1<<<NBLK1, 256>>>();
    k_scan2<<<1, 512>>>();
    k_scan3<<<NBLK1, 256>>>();
    k_fill<<<(EE + 255) / 256, 256>>>(eidx);

    // 1) weight transpose + split; x -> fp16 gather table
    k_wsplit<<<(INC * HIDC + 255) / 256, 256>>>(W1l, wh + WO_1L, wl + WO_1L, INC, HIDC);
    k_wsplit<<<(INC * HIDC + 255) / 256, 256>>>(W1r, wh + WO_1R, wl + WO_1R, INC, HIDC);
    k_wsplit<<<(HIDC * HIDC + 255) / 256, 256>>>(W2l, wh + WO_2L, wl + WO_2L, HIDC, HIDC);
    k_wsplit<<<(HIDC * HIDC + 255) / 256, 256>>>(W2r, wh + WO_2R, wl + WO_2R, HIDC, HIDC);
    k_wsplit<<<(HIDC * OUTC + 255) / 256, 256>>>(Wcl, wh + WO_CL, wl + WO_CL, HIDC, OUTC);
    k_wsplit<<<(HIDC * OUTC + 255) / 256, 256>>>(Wcr, wh + WO_CR, wl + WO_CR, HIDC, OUTC);
    k_tohalf<<<4096, 256>>>(x, p_xh, (long long)NN * INC / 2);

    const int MBLK = (NN + 127) / 128;  // 782
    const int AGG_BLOCKS = (NN + 7) / 8;

    // 2) layer 1 (grid transposed: x = n-tiles, y = m-tiles)
    k_agg<INC / 32, false><<<AGG_BLOCKS, 256>>>(p_xh, nullptr, p_msg);
    k_mgemm<INC, HIDC, 2, true, true, false, true><<<dim3(HIDC / 64, MBLK), 256, DSMEM>>>(
        p_msg, x, wh + WO_1L, wl + WO_1L, wh + WO_1R, wl + WO_1R,
        b1l, g1, be1, rm1, rv1, p_h1, nullptr, p_h1h);

    // 3) layer 2
    k_agg<HIDC / 32, false><<<AGG_BLOCKS, 256>>>(p_h1h, nullptr, p_msg);
    k_mgemm<HIDC, HIDC, 2, true, true, false, false><<<dim3(HIDC / 64, MBLK), 256, DSMEM>>>(
        p_msg, p_h1, wh + WO_2L, wl + WO_2L, wh + WO_2R, wl + WO_2R,
        b2l, g2, be2, rm2, rv2, p_h2, nullptr, nullptr);

    // 4) layer 3: dual GEMM (t -> fp16 table, r = h2@Wcr + bcl), out = agg(t)+r
    k_mgemm<HIDC, 128, 1, true, false, true, false><<<dim3(2, MBLK), 256, DSMEM>>>(
        p_h2, nullptr, wh + WO_CL, wl + WO_CL, nullptr, nullptr,
        bcl, nullptr, nullptr, nullptr, nullptr, nullptr, p_r, p_th);
    k_agg<OUTC / 32, true><<<AGG_BLOCKS, 256>>>(p_th, p_r, out);
}

// round 11
// speedup vs baseline: 1.2978x; 1.0858x over previous
#include <cuda_runtime.h>
#include <cuda_bf16.h>
#include <cuda_fp16.h>
#include <cstdint>

#define NN 100000
#define EE 1600000
#define INC 128
#define HIDC 256
#define OUTC 64
#define FEPS 1e-5f
#define NBLK1 ((NN + 255) / 256)

// ---------------- scratch ----------------------------------------------------
__device__ int   g_is64;
__device__ int   g_degi[NN];
__device__ int   g_incl[NN];
__device__ int   g_bsum[512];
__device__ int   g_boff[512];
__device__ int   g_rowptr[NN];
__device__ int   g_cursor[NN];
__device__ int   g_csrc[EE];
__device__ float g_r[(size_t)NN * OUTC];
// fp16 tables (entire inter-kernel dataflow)
__device__ __half g_xh[(size_t)NN * INC];
__device__ __half g_msgh[(size_t)NN * HIDC];
__device__ __half g_h1h[(size_t)NN * HIDC];
__device__ __half g_h2h[(size_t)NN * HIDC];
__device__ __half g_th[(size_t)NN * OUTC];
// transposed, split weights, [N][K] layout.
#define WO_1L 0
#define WO_1R 32768
#define WO_2L 65536
#define WO_2R 131072
#define WO_CL 196608
#define WO_CR 212992
__device__ __nv_bfloat16 g_wh[229376];
__device__ __nv_bfloat16 g_wl[229376];

// ---------------- PTX helpers ------------------------------------------------
__device__ __forceinline__ uint32_t smem_u32(const void* p) {
    uint32_t a;
    asm("{ .reg .u64 t; cvta.to.shared.u64 t, %1; cvt.u32.u64 %0, t; }"
        : "=r"(a) : "l"(p));
    return a;
}
#define LDSM4(r, addr)                                                          \
    asm volatile("ldmatrix.sync.aligned.m8n8.x4.shared.b16 {%0,%1,%2,%3}, [%4];"\
                 : "=r"((r)[0]), "=r"((r)[1]), "=r"((r)[2]), "=r"((r)[3])       \
                 : "r"(addr))
#define LDSM2(r, addr)                                                          \
    asm volatile("ldmatrix.sync.aligned.m8n8.x2.shared.b16 {%0,%1}, [%2];"      \
                 : "=r"((r)[0]), "=r"((r)[1]) : "r"(addr))
#define MMA16816(d, a, b)                                                       \
    asm volatile("mma.sync.aligned.m16n8k16.row.col.f32.bf16.bf16.f32 "         \
                 "{%0,%1,%2,%3}, {%4,%5,%6,%7}, {%8,%9}, {%0,%1,%2,%3};"        \
                 : "+f"((d)[0]), "+f"((d)[1]), "+f"((d)[2]), "+f"((d)[3])       \
                 : "r"((a)[0]), "r"((a)[1]), "r"((a)[2]), "r"((a)[3]),          \
                   "r"((b)[0]), "r"((b)[1]))

// ---------------- misc kernels ----------------------------------------------
__device__ __forceinline__ int load_idx(const void* base, long long i) {
    if (g_is64) return (int)((const long long*)base)[i];
    return ((const int*)base)[i];
}
__global__ void k_zero_detect(int* p, int n, const int* e32) {
    int i = blockIdx.x * blockDim.x + threadIdx.x;
    if (i < n) p[i] = 0;
    if (blockIdx.x == 0 && threadIdx.x == 0) {
        int is64 = 1;
        for (int q = 0; q < 32; q++)
            if (e32[2 * q + 1] != 0) is64 = 0;
        g_is64 = is64;
    }
}
__global__ void k_degi(const void* eidx) {
    int e = blockIdx.x * blockDim.x + threadIdx.x;
    if (e < EE) atomicAdd(&g_degi[load_idx(eidx, (long long)EE + e)], 1);
}
__global__ void k_scan1() {
    __shared__ int s[256];
    int i = blockIdx.x * 256 + threadIdx.x;
    int v = (i < NN) ? g_degi[i] : 0;
    s[threadIdx.x] = v;
    __syncthreads();
#pragma unroll
    for (int off = 1; off < 256; off <<= 1) {
        int t = (threadIdx.x >= off) ? s[threadIdx.x - off] : 0;
        __syncthreads();
        s[threadIdx.x] += t;
        __syncthreads();
    }
    if (i < NN) g_incl[i] = s[threadIdx.x];
    if (threadIdx.x == 255) g_bsum[blockIdx.x] = s[255];
}
__global__ void k_scan2() {
    __shared__ int s[512];
    int tid = threadIdx.x;
    s[tid] = (tid < NBLK1) ? g_bsum[tid] : 0;
    __syncthreads();
#pragma unroll
    for (int off = 1; off < 512; off <<= 1) {
        int t = (tid >= off) ? s[tid - off] : 0;
        __syncthreads();
        s[tid] += t;
        __syncthreads();
    }
    g_boff[tid] = s[tid];
}
__global__ void k_scan3() {
    int i = blockIdx.x * 256 + threadIdx.x;
    if (i < NN) {
        int off = (blockIdx.x > 0) ? g_boff[blockIdx.x - 1] : 0;
        int start = off + g_incl[i] - g_degi[i];
        g_rowptr[i] = start;
        g_cursor[i] = start;
    }
}
__global__ void k_fill(const void* eidx) {
    int e = blockIdx.x * blockDim.x + threadIdx.x;
    if (e < EE) {
        int s = load_idx(eidx, e);
        int d = load_idx(eidx, (long long)EE + e);
        g_csrc[atomicAdd(&g_cursor[d], 1)] = s;
    }
}
__global__ void k_tohalf(const float* __restrict__ in, __half* __restrict__ out,
                         long long n2) {
    long long i = (long long)blockIdx.x * blockDim.x + threadIdx.x;
    long long stride = (long long)gridDim.x * blockDim.x;
    const float2* in2 = (const float2*)in;
    __half2* out2 = (__half2*)out;
    for (; i < n2; i += stride) out2[i] = __float22half2_rn(in2[i]);
}

// ---------------- gather mean aggregation (fp16 in, fp16 or fp32 out) --------
template <int CH>
__device__ __forceinline__ void vloadh(float (&r)[CH], const __half* p) {
    uint32_t u[CH / 2];
    if (CH == 2) {
        u[0] = *(const uint32_t*)p;
    } else if (CH == 4) {
        uint2 v = *(const uint2*)p;
        u[0] = v.x; u[1] = v.y;
    } else {
        uint4 v = *(const uint4*)p;
        u[0] = v.x; u[1] = v.y; u[2] = v.z; u[3] = v.w;
    }
#pragma unroll
    for (int q = 0; q < CH / 2; q++) {
        __half2 h = *(__half2*)&u[q];
        float2 f = __half22float2(h);
        r[2 * q + 0] = f.x;
        r[2 * q + 1] = f.y;
    }
}
template <int CH>
__device__ __forceinline__ void vload(float (&r)[CH], const float* p) {
    if (CH == 2) {
        float2 v = *(const float2*)p;
        r[0] = v.x; r[1] = v.y;
    } else {
#pragma unroll
        for (int q = 0; q < CH / 4; q++) {
            float4 v = *(const float4*)(p + q * 4);
            r[q * 4 + 0] = v.x; r[q * 4 + 1] = v.y;
            r[q * 4 + 2] = v.z; r[q * 4 + 3] = v.w;
        }
    }
}
template <int CH>
__device__ __forceinline__ void vstore(float* p, const float (&r)[CH]) {
    if (CH == 2) {
        *(float2*)p = make_float2(r[0], r[1]);
    } else {
#pragma unroll
        for (int q = 0; q < CH / 4; q++)
            *(float4*)(p + q * 4) =
                make_float4(r[q * 4 + 0], r[q * 4 + 1], r[q * 4 + 2], r[q * 4 + 3]);
    }
}
template <int CH>
__device__ __forceinline__ void vstoreh(__half* p, const float (&r)[CH]) {
    uint32_t u[CH / 2];
#pragma unroll
    for (int q = 0; q < CH / 2; q++) {
        __half2 h = __floats2half2_rn(r[2 * q + 0], r[2 * q + 1]);
        u[q] = *(uint32_t*)&h;
    }
    if (CH == 2) {
        *(uint32_t*)p = u[0];
    } else if (CH == 4) {
        *(uint2*)p = make_uint2(u[0], u[1]);
    } else {
        *(uint4*)p = make_uint4(u[0], u[1], u[2], u[3]);
    }
}

// OUTH: write fp16 table; else fp32 (final layer, with extra add)
template <int CH, bool OUTH, bool ADD_EXTRA>
__global__ void k_agg(const __half* __restrict__ feat,
                      const float* __restrict__ extra,
                      __half* __restrict__ outh,
                      float* __restrict__ outf) {
    const int D = 32 * CH;
    int warp = (blockIdx.x * blockDim.x + threadIdx.x) >> 5;
    int lane = threadIdx.x & 31;
    if (warp >= NN) return;
    int start = g_rowptr[warp];
    int dg = g_degi[warp];
    const __half* fb = feat + lane * CH;

    float acc[CH];
#pragma unroll
    for (int v = 0; v < CH; v++) acc[v] = 0.0f;

    int j = 0;
    for (; j + 4 <= dg; j += 4) {
        int s0 = g_csrc[start + j + 0];
        int s1 = g_csrc[start + j + 1];
        int s2 = g_csrc[start + j + 2];
        int s3 = g_csrc[start + j + 3];
        float r0[CH], r1[CH], r2[CH], r3[CH];
        vloadh<CH>(r0, fb + (long long)s0 * D);
        vloadh<CH>(r1, fb + (long long)s1 * D);
        vloadh<CH>(r2, fb + (long long)s2 * D);
        vloadh<CH>(r3, fb + (long long)s3 * D);
#pragma unroll
        for (int v = 0; v < CH; v++) acc[v] += r0[v];
#pragma unroll
        for (int v = 0; v < CH; v++) acc[v] += r1[v];
#pragma unroll
        for (int v = 0; v < CH; v++) acc[v] += r2[v];
#pragma unroll
        for (int v = 0; v < CH; v++) acc[v] += r3[v];
    }
    for (; j < dg; j++) {
        int s0 = g_csrc[start + j];
        float r0[CH];
        vloadh<CH>(r0, fb + (long long)s0 * D);
#pragma unroll
        for (int v = 0; v < CH; v++) acc[v] += r0[v];
    }

    float inv = (dg > 0) ? (1.0f / (float)dg) : 0.0f;
#pragma unroll
    for (int v = 0; v < CH; v++) acc[v] *= inv;
    if (ADD_EXTRA) {
        float ex[CH];
        vload<CH>(ex, extra + (long long)warp * D + lane * CH);
#pragma unroll
        for (int v = 0; v < CH; v++) acc[v] += ex[v];
    }
    if (OUTH)
        vstoreh<CH>(outh + (long long)warp * D + lane * CH, acc);
    else
        vstore<CH>(outf + (long long)warp * D + lane * CH, acc);
}

// W[K,N] fp32 -> Wt[N,K] bf16 hi/lo
__global__ void k_wsplit(const float* __restrict__ W,
                         __nv_bfloat16* __restrict__ th,
                         __nv_bfloat16* __restrict__ tl, int K, int N) {
    int i = blockIdx.x * blockDim.x + threadIdx.x;
    if (i < K * N) {
        int k = i / N, n = i % N;
        float v = W[i];
        __nv_bfloat16 h = __float2bfloat16(v);
        th[n * K + k] = h;
        tl[n * K + k] = __float2bfloat16(v - __bfloat162float(h));
    }
}

// ---------------- mma.sync bf16-split GEMM, A fp16, BM=128 BN=64, 2-stage ----
// A (fp16) split exactly into bf16 hi/lo during smem fill (fp16 = hi+lo exact).
// F16ONLY: epilogue writes fp16 table Th only (layers 1-2).
// DUAL: cols [0,64) -> fp16 Th; [64,128) -> fp32 C2 (+bias) (layer 3).
#define ASTR 40
#define OAH 0
#define OAL 10240
#define OBH 20480
#define OBL 25600
#define BUFB 30720
template <int KTOT, int NOUT, int NMAT, bool HAS_BIAS, bool BN, bool DUAL, bool F16ONLY>
__global__ void __launch_bounds__(256) k_mgemm(
    const __half* __restrict__ A1, const __half* __restrict__ A2,
    const __nv_bfloat16* __restrict__ B1h, const __nv_bfloat16* __restrict__ B1l,
    const __nv_bfloat16* __restrict__ B2h, const __nv_bfloat16* __restrict__ B2l,
    const float* __restrict__ bias, const float* __restrict__ gamma,
    const float* __restrict__ beta, const float* __restrict__ rm,
    const float* __restrict__ rv,
    float* __restrict__ C2, __half* __restrict__ Th) {
    extern __shared__ __align__(16) char dsm[];

    const int tid = threadIdx.x;
    const int lane = tid & 31;
    const int wid = tid >> 5;
    const int wm = wid & 3;
    const int wn = wid >> 2;
    const long long bm = (long long)blockIdx.y * 128;
    const int bn = blockIdx.x * 64;
    const int KC = KTOT / 32;
    const int TOT = NMAT * KC;

    float acc[2][4][4];
#pragma unroll
    for (int i = 0; i < 2; i++)
#pragma unroll
        for (int j = 0; j < 4; j++)
#pragma unroll
            for (int q = 0; q < 4; q++) acc[i][j][q] = 0.0f;

    const uint32_t sb = smem_u32(dsm);
    const uint32_t loA = (((wm * 32 + (lane & 15)) * ASTR + ((lane >> 4) << 3)) << 1);
    const uint32_t loB = (((wn * 32 + (lane & 7)) * ASTR + (((lane >> 3) & 1) << 3)) << 1);

    uint4 aR[2];   // A tile: 128x32 fp16 = 8KB; 256 thr x 2 x 16B
    uint4 bhR, blR;

#define LOAD_ITER(it) do {                                                       \
    int _m = (it) / KC, _kc = (it) % KC, _k0 = _kc * 32;                         \
    const __half* _A = (_m == 0) ? A1 : A2;                                      \
    const __nv_bfloat16* _Bh = (_m == 0) ? B1h : B2h;                            \
    const __nv_bfloat16* _Bl = (_m == 0) ? B1l : B2l;                            \
    _Pragma("unroll")                                                            \
    for (int _i = 0; _i < 2; _i++) {                                             \
        int _s = tid + _i * 256;                                                 \
        int _r = _s >> 2, _c = _s & 3;                                           \
        long long _grow = bm + _r;                                               \
        uint4 _v = make_uint4(0, 0, 0, 0);                                       \
        if (_grow < NN) _v = *(const uint4*)(_A + _grow * KTOT + _k0 + _c * 8);  \
        aR[_i] = _v;                                                             \
    }                                                                            \
    {                                                                            \
        int _r = tid >> 2, _c = tid & 3;                                         \
        long long _off = (long long)(bn + _r) * KTOT + _k0 + _c * 8;             \
        bhR = *(const uint4*)(_Bh + _off);                                       \
        blR = *(const uint4*)(_Bl + _off);                                       \
    }                                                                            \
} while (0)

// convert 2 halves (packed u32) -> packed bf16 hi pair + lo pair
#define SPLIT2(hout, lout, hin) do {                                             \
    __half2 _hh = *(__half2*)&(hin);                                             \
    float2 _ff = __half22float2(_hh);                                            \
    __nv_bfloat16 _b0 = __float2bfloat16(_ff.x);                                 \
    __nv_bfloat16 _b1 = __float2bfloat16(_ff.y);                                 \
    __nv_bfloat16 _c0 = __float2bfloat16(_ff.x - __bfloat162float(_b0));         \
    __nv_bfloat16 _c1 = __float2bfloat16(_ff.y - __bfloat162float(_b1));         \
    (hout) = ((uint32_t)__bfloat16_as_ushort(_b1) << 16) |                       \
             __bfloat16_as_ushort(_b0);                                          \
    (lout) = ((uint32_t)__bfloat16_as_ushort(_c1) << 16) |                       \
             __bfloat16_as_ushort(_c0);                                          \
} while (0)

#define STORE_ITER(buf) do {                                                     \
    char* _S = dsm + (buf) * BUFB;                                               \
    _Pragma("unroll")                                                            \
    for (int _i = 0; _i < 2; _i++) {                                             \
        int _s = tid + _i * 256;                                                 \
        int _r = _s >> 2, _c = _s & 3;                                           \
        uint32_t _u[4] = {aR[_i].x, aR[_i].y, aR[_i].z, aR[_i].w};               \
        uint32_t _h[4], _l[4];                                                   \
        SPLIT2(_h[0], _l[0], _u[0]);                                             \
        SPLIT2(_h[1], _l[1], _u[1]);                                             \
        SPLIT2(_h[2], _l[2], _u[2]);                                             \
        SPLIT2(_h[3], _l[3], _u[3]);                                             \
        *(uint4*)(_S + OAH + (_r * ASTR + _c * 8) * 2) =                         \
            make_uint4(_h[0], _h[1], _h[2], _h[3]);                              \
        *(uint4*)(_S + OAL + (_r * ASTR + _c * 8) * 2) =                         \
            make_uint4(_l[0], _l[1], _l[2], _l[3]);                              \
    }                                                                            \
    {                                                                            \
        int _r = tid >> 2, _c = tid & 3;                                         \
        *(uint4*)(_S + OBH + (_r * ASTR + _c * 8) * 2) = bhR;                    \
        *(uint4*)(_S + OBL + (_r * ASTR + _c * 8) * 2) = blR;                    \
    }                                                                            \
} while (0)

#define COMPUTE(buf) do {                                                        \
    const uint32_t _b = sb + (buf) * BUFB;                                       \
    const uint32_t _aAh = _b + OAH + loA;                                        \
    const uint32_t _aAl = _b + OAL + loA;                                        \
    const uint32_t _aBh = _b + OBH + loB;                                        \
    const uint32_t _aBl = _b + OBL + loB;                                        \
    _Pragma("unroll")                                                            \
    for (int _ka = 0; _ka < 2; _ka++) {                                          \
        const uint32_t _ko = _ka * 32;                                           \
        uint32_t _ah[2][4], _al[2][4], _bh[4][2], _bl[4][2];                     \
        LDSM4(_ah[0], _aAh + _ko);                                               \
        LDSM4(_ah[1], _aAh + 1280 + _ko);                                        \
        LDSM4(_al[0], _aAl + _ko);                                               \
        LDSM4(_al[1], _aAl + 1280 + _ko);                                        \
        _Pragma("unroll")                                                        \
        for (int _na = 0; _na < 4; _na++) {                                      \
            LDSM2(_bh[_na], _aBh + _na * 640 + _ko);                             \
            LDSM2(_bl[_na], _aBl + _na * 640 + _ko);                             \
        }                                                                        \
        _Pragma("unroll")                                                        \
        for (int _ma = 0; _ma < 2; _ma++)                                        \
            _Pragma("unroll")                                                    \
            for (int _na = 0; _na < 4; _na++) {                                  \
                MMA16816(acc[_ma][_na], _ah[_ma], _bh[_na]);                     \
                MMA16816(acc[_ma][_na], _ah[_ma], _bl[_na]);                     \
                MMA16816(acc[_ma][_na], _al[_ma], _bh[_na]);                     \
            }                                                                    \
    }                                                                            \
} while (0)

    LOAD_ITER(0);
    STORE_ITER(0);
    __syncthreads();
    for (int it = 0; it < TOT; it++) {
        const int cur = it & 1;
        if (it + 1 < TOT) LOAD_ITER(it + 1);
        COMPUTE(cur);
        if (it + 1 < TOT) STORE_ITER(cur ^ 1);
        __syncthreads();
    }

    const int g = lane >> 2, t = lane & 3;
#pragma unroll
    for (int ma = 0; ma < 2; ma++) {
#pragma unroll
        for (int na = 0; na < 4; na++) {
            int lcol = wn * 32 + na * 8 + 2 * t;
            int gc = bn + lcol;
#pragma unroll
            for (int half = 0; half < 2; half++) {
                long long row = bm + wm * 32 + ma * 16 + g + half * 8;
                if (row >= NN) continue;
                float v0 = acc[ma][na][half * 2 + 0];
                float v1 = acc[ma][na][half * 2 + 1];
                if (DUAL) {
                    if (gc < 64) {
                        *(__half2*)&Th[row * 64 + gc] = __floats2half2_rn(v0, v1);
                    } else {
                        C2[row * 64 + gc - 64] = v0 + bias[gc - 64];
                        C2[row * 64 + gc - 63] = v1 + bias[gc - 63];
                    }
                } else {
                    if (HAS_BIAS) { v0 += bias[gc]; v1 += bias[gc + 1]; }
                    if (BN) {
                        v0 = (v0 - rm[gc]) * rsqrtf(rv[gc] + FEPS) * gamma[gc] + beta[gc];
                        v1 = (v1 - rm[gc + 1]) * rsqrtf(rv[gc + 1] + FEPS) * gamma[gc + 1] + beta[gc + 1];
                        v0 = fmaxf(v0, 0.0f);
                        v1 = fmaxf(v1, 0.0f);
                    }
                    // F16ONLY: fp16 table is the sole consumer format
                    *(__half2*)&Th[row * NOUT + gc] = __floats2half2_rn(v0, v1);
                }
            }
        }
    }
#undef LOAD_ITER
#undef STORE_ITER
#undef COMPUTE
#undef SPLIT2
}

// ---------------- launch ----------------------------------------------------
extern "C" void kernel_launch(void* const* d_in, const int* in_sizes, int n_in,
                              void* d_out, int out_size) {
    const float* x    = (const float*)d_in[0];
    const void*  eidx = d_in[1];
    const float* W1l  = (const float*)d_in[2];
    const float* b1l  = (const float*)d_in[3];
    const float* W1r  = (const float*)d_in[4];
    const float* g1   = (const float*)d_in[5];
    const float* be1  = (const float*)d_in[6];
    const float* rm1  = (const float*)d_in[7];
    const float* rv1  = (const float*)d_in[8];
    const float* W2l  = (const float*)d_in[9];
    const float* b2l  = (const float*)d_in[10];
    const float* W2r  = (const float*)d_in[11];
    const float* g2   = (const float*)d_in[12];
    const float* be2  = (const float*)d_in[13];
    const float* rm2  = (const float*)d_in[14];
    const float* rv2  = (const float*)d_in[15];
    const float* Wcl  = (const float*)d_in[16];
    const float* bcl  = (const float*)d_in[17];
    const float* Wcr  = (const float*)d_in[18];
    float* out = (float*)d_out;

    int* p_degi;        cudaGetSymbolAddress((void**)&p_degi, g_degi);
    float* p_r;         cudaGetSymbolAddress((void**)&p_r, g_r);
    __half* p_xh;       cudaGetSymbolAddress((void**)&p_xh, g_xh);
    __half* p_msgh;     cudaGetSymbolAddress((void**)&p_msgh, g_msgh);
    __half* p_h1h;      cudaGetSymbolAddress((void**)&p_h1h, g_h1h);
    __half* p_h2h;      cudaGetSymbolAddress((void**)&p_h2h, g_h2h);
    __half* p_th;       cudaGetSymbolAddress((void**)&p_th, g_th);
    __nv_bfloat16* wh;  cudaGetSymbolAddress((void**)&wh, g_wh);
    __nv_bfloat16* wl;  cudaGetSymbolAddress((void**)&wl, g_wl);

    const int DSMEM = 2 * BUFB;  // 61440
    cudaFuncSetAttribute(k_mgemm<INC, HIDC, 2, true, true, false, true>,
                         cudaFuncAttributeMaxDynamicSharedMemorySize, DSMEM);
    cudaFuncSetAttribute(k_mgemm<HIDC, HIDC, 2, true, true, false, true>,
                         cudaFuncAttributeMaxDynamicSharedMemorySize, DSMEM);
    cudaFuncSetAttribute(k_mgemm<HIDC, 128, 1, true, false, true, false>,
                         cudaFuncAttributeMaxDynamicSharedMemorySize, DSMEM);

    // 0) CSR build
    k_zero_detect<<<NBLK1, 256>>>(p_degi, NN, (const int*)eidx);
    k_degi<<<(EE + 255) / 256, 256>>>(eidx);
    k_scan1<<<NBLK1, 256>>>();
    k_scan2<<<1, 512>>>();
    k_scan3<<<NBLK1, 256>>>();
    k_fill<<<(EE + 255) / 256, 256>>>(eidx);

    // 1) weight transpose + split; x -> fp16 table
    k_wsplit<<<(INC * HIDC + 255) / 256, 256>>>(W1l, wh + WO_1L, wl + WO_1L, INC, HIDC);
    k_wsplit<<<(INC * HIDC + 255) / 256, 256>>>(W1r, wh + WO_1R, wl + WO_1R, INC, HIDC);
    k_wsplit<<<(HIDC * HIDC + 255) / 256, 256>>>(W2l, wh + WO_2L, wl + WO_2L, HIDC, HIDC);
    k_wsplit<<<(HIDC * HIDC + 255) / 256, 256>>>(W2r, wh + WO_2R, wl + WO_2R, HIDC, HIDC);
    k_wsplit<<<(HIDC * OUTC + 255) / 256, 256>>>(Wcl, wh + WO_CL, wl + WO_CL, HIDC, OUTC);
    k_wsplit<<<(HIDC * OUTC + 255) / 256, 256>>>(Wcr, wh + WO_CR, wl + WO_CR, HIDC, OUTC);
    k_tohalf<<<4096, 256>>>(x, p_xh, (long long)NN * INC / 2);

    const int MBLK = (NN + 127) / 128;  // 782
    const int AGG_BLOCKS = (NN + 7) / 8;

    // 2) layer 1: agg(xh)->msgh fp16; GEMM(A fp16) -> h1h fp16 only
    k_agg<INC / 32, true, false><<<AGG_BLOCKS, 256>>>(p_xh, nullptr, p_msgh, nullptr);
    k_mgemm<INC, HIDC, 2, true, true, false, true><<<dim3(HIDC / 64, MBLK), 256, DSMEM>>>(
        p_msgh, p_xh, wh + WO_1L, wl + WO_1L, wh + WO_1R, wl + WO_1R,
        b1l, g1, be1, rm1, rv1, nullptr, p_h1h);

    // 3) layer 2: agg(h1h)->msgh; GEMM -> h2h fp16 only
    k_agg<HIDC / 32, true, false><<<AGG_BLOCKS, 256>>>(p_h1h, nullptr, p_msgh, nullptr);
    k_mgemm<HIDC, HIDC, 2, true, true, false, true><<<dim3(HIDC / 64, MBLK), 256, DSMEM>>>(
        p_msgh, p_h1h, wh + WO_2L, wl + WO_2L, wh + WO_2R, wl + WO_2R,
        b2l, g2, be2, rm2, rv2, nullptr, p_h2h);

    // 4) layer 3: dual GEMM (t -> fp16 th, r = h2@Wcr + bcl fp32); out = agg(t)+r
    k_mgemm<HIDC, 128, 1, true, false, true, false><<<dim3(2, MBLK), 256, DSMEM>>>(
        p_h2h, nullptr, wh + WO_CL, wl + WO_CL, nullptr, nullptr,
        bcl, nullptr, nullptr, nullptr, nullptr, p_r, p_th);
    k_agg<OUTC / 32, false, true><<<AGG_BLOCKS, 256>>>(p_th, p_r, nullptr, out);
}

// round 12
// speedup vs baseline: 1.5556x; 1.1987x over previous
#include <cuda_runtime.h>
#include <cuda_fp16.h>
#include <cstdint>

#define NN 100000
#define EE 1600000
#define INC 128
#define HIDC 256
#define OUTC 64
#define FEPS 1e-5f
#define NBLK1 ((NN + 255) / 256)

// ---------------- scratch ----------------------------------------------------
__device__ int   g_is64;
__device__ int   g_degi[NN];
__device__ int   g_incl[NN];
__device__ int   g_bsum[512];
__device__ int   g_boff[512];
__device__ int   g_rowptr[NN];
__device__ int   g_cursor[NN];
__device__ int   g_csrc[EE];
__device__ float g_r[(size_t)NN * OUTC];
// fp16 tables (entire inter-kernel dataflow)
__device__ __half g_xh[(size_t)NN * INC];
__device__ __half g_msgh[(size_t)NN * HIDC];
__device__ __half g_h1h[(size_t)NN * HIDC];
__device__ __half g_h2h[(size_t)NN * HIDC];
__device__ __half g_th[(size_t)NN * OUTC];
// transposed weights, [N][K] layout, fp16 hi + fp16 lo (22-bit mantissa total)
#define WO_1L 0
#define WO_1R 32768
#define WO_2L 65536
#define WO_2R 131072
#define WO_CL 196608
#define WO_CR 212992
__device__ __half g_wh[229376];
__device__ __half g_wl[229376];

// ---------------- PTX helpers ------------------------------------------------
__device__ __forceinline__ uint32_t smem_u32(const void* p) {
    uint32_t a;
    asm("{ .reg .u64 t; cvta.to.shared.u64 t, %1; cvt.u32.u64 %0, t; }"
        : "=r"(a) : "l"(p));
    return a;
}
#define LDSM4(r, addr)                                                          \
    asm volatile("ldmatrix.sync.aligned.m8n8.x4.shared.b16 {%0,%1,%2,%3}, [%4];"\
                 : "=r"((r)[0]), "=r"((r)[1]), "=r"((r)[2]), "=r"((r)[3])       \
                 : "r"(addr))
#define LDSM2(r, addr)                                                          \
    asm volatile("ldmatrix.sync.aligned.m8n8.x2.shared.b16 {%0,%1}, [%2];"      \
                 : "=r"((r)[0]), "=r"((r)[1]) : "r"(addr))
// fp16 x fp16 -> fp32 accumulate: products exact (11+11 <= 24 bits)
#define MMA16816(d, a, b)                                                       \
    asm volatile("mma.sync.aligned.m16n8k16.row.col.f32.f16.f16.f32 "           \
                 "{%0,%1,%2,%3}, {%4,%5,%6,%7}, {%8,%9}, {%0,%1,%2,%3};"        \
                 : "+f"((d)[0]), "+f"((d)[1]), "+f"((d)[2]), "+f"((d)[3])       \
                 : "r"((a)[0]), "r"((a)[1]), "r"((a)[2]), "r"((a)[3]),          \
                   "r"((b)[0]), "r"((b)[1]))

// ---------------- misc kernels ----------------------------------------------
__device__ __forceinline__ int load_idx(const void* base, long long i) {
    if (g_is64) return (int)((const long long*)base)[i];
    return ((const int*)base)[i];
}
__global__ void k_zero_detect(int* p, int n, const int* e32) {
    int i = blockIdx.x * blockDim.x + threadIdx.x;
    if (i < n) p[i] = 0;
    if (blockIdx.x == 0 && threadIdx.x == 0) {
        int is64 = 1;
        for (int q = 0; q < 32; q++)
            if (e32[2 * q + 1] != 0) is64 = 0;
        g_is64 = is64;
    }
}
__global__ void k_degi(const void* eidx) {
    int e = blockIdx.x * blockDim.x + threadIdx.x;
    if (e < EE) atomicAdd(&g_degi[load_idx(eidx, (long long)EE + e)], 1);
}
__global__ void k_scan1() {
    __shared__ int s[256];
    int i = blockIdx.x * 256 + threadIdx.x;
    int v = (i < NN) ? g_degi[i] : 0;
    s[threadIdx.x] = v;
    __syncthreads();
#pragma unroll
    for (int off = 1; off < 256; off <<= 1) {
        int t = (threadIdx.x >= off) ? s[threadIdx.x - off] : 0;
        __syncthreads();
        s[threadIdx.x] += t;
        __syncthreads();
    }
    if (i < NN) g_incl[i] = s[threadIdx.x];
    if (threadIdx.x == 255) g_bsum[blockIdx.x] = s[255];
}
__global__ void k_scan2() {
    __shared__ int s[512];
    int tid = threadIdx.x;
    s[tid] = (tid < NBLK1) ? g_bsum[tid] : 0;
    __syncthreads();
#pragma unroll
    for (int off = 1; off < 512; off <<= 1) {
        int t = (tid >= off) ? s[tid - off] : 0;
        __syncthreads();
        s[tid] += t;
        __syncthreads();
    }
    g_boff[tid] = s[tid];
}
__global__ void k_scan3() {
    int i = blockIdx.x * 256 + threadIdx.x;
    if (i < NN) {
        int off = (blockIdx.x > 0) ? g_boff[blockIdx.x - 1] : 0;
        int start = off + g_incl[i] - g_degi[i];
        g_rowptr[i] = start;
        g_cursor[i] = start;
    }
}
__global__ void k_fill(const void* eidx) {
    int e = blockIdx.x * blockDim.x + threadIdx.x;
    if (e < EE) {
        int s = load_idx(eidx, e);
        int d = load_idx(eidx, (long long)EE + e);
        g_csrc[atomicAdd(&g_cursor[d], 1)] = s;
    }
}
__global__ void k_tohalf(const float* __restrict__ in, __half* __restrict__ out,
                         long long n2) {
    long long i = (long long)blockIdx.x * blockDim.x + threadIdx.x;
    long long stride = (long long)gridDim.x * blockDim.x;
    const float2* in2 = (const float2*)in;
    __half2* out2 = (__half2*)out;
    for (; i < n2; i += stride) out2[i] = __float22half2_rn(in2[i]);
}

// ---------------- gather mean aggregation (fp16 in, fp16 or fp32 out) --------
template <int CH>
__device__ __forceinline__ void vloadh(float (&r)[CH], const __half* p) {
    uint32_t u[CH / 2];
    if (CH == 2) {
        u[0] = *(const uint32_t*)p;
    } else if (CH == 4) {
        uint2 v = *(const uint2*)p;
        u[0] = v.x; u[1] = v.y;
    } else {
        uint4 v = *(const uint4*)p;
        u[0] = v.x; u[1] = v.y; u[2] = v.z; u[3] = v.w;
    }
#pragma unroll
    for (int q = 0; q < CH / 2; q++) {
        __half2 h = *(__half2*)&u[q];
        float2 f = __half22float2(h);
        r[2 * q + 0] = f.x;
        r[2 * q + 1] = f.y;
    }
}
template <int CH>
__device__ __forceinline__ void vload(float (&r)[CH], const float* p) {
    if (CH == 2) {
        float2 v = *(const float2*)p;
        r[0] = v.x; r[1] = v.y;
    } else {
#pragma unroll
        for (int q = 0; q < CH / 4; q++) {
            float4 v = *(const float4*)(p + q * 4);
            r[q * 4 + 0] = v.x; r[q * 4 + 1] = v.y;
            r[q * 4 + 2] = v.z; r[q * 4 + 3] = v.w;
        }
    }
}
template <int CH>
__device__ __forceinline__ void vstore(float* p, const float (&r)[CH]) {
    if (CH == 2) {
        *(float2*)p = make_float2(r[0], r[1]);
    } else {
#pragma unroll
        for (int q = 0; q < CH / 4; q++)
            *(float4*)(p + q * 4) =
                make_float4(r[q * 4 + 0], r[q * 4 + 1], r[q * 4 + 2], r[q * 4 + 3]);
    }
}
template <int CH>
__device__ __forceinline__ void vstoreh(__half* p, const float (&r)[CH]) {
    uint32_t u[CH / 2];
#pragma unroll
    for (int q = 0; q < CH / 2; q++) {
        __half2 h = __floats2half2_rn(r[2 * q + 0], r[2 * q + 1]);
        u[q] = *(uint32_t*)&h;
    }
    if (CH == 2) {
        *(uint32_t*)p = u[0];
    } else if (CH == 4) {
        *(uint2*)p = make_uint2(u[0], u[1]);
    } else {
        *(uint4*)p = make_uint4(u[0], u[1], u[2], u[3]);
    }
}

template <int CH, bool OUTH, bool ADD_EXTRA>
__global__ void k_agg(const __half* __restrict__ feat,
                      const float* __restrict__ extra,
                      __half* __restrict__ outh,
                      float* __restrict__ outf) {
    const int D = 32 * CH;
    int warp = (blockIdx.x * blockDim.x + threadIdx.x) >> 5;
    int lane = threadIdx.x & 31;
    if (warp >= NN) return;
    int start = g_rowptr[warp];
    int dg = g_degi[warp];
    const __half* fb = feat + lane * CH;

    float acc[CH];
#pragma unroll
    for (int v = 0; v < CH; v++) acc[v] = 0.0f;

    int j = 0;
    for (; j + 4 <= dg; j += 4) {
        int s0 = g_csrc[start + j + 0];
        int s1 = g_csrc[start + j + 1];
        int s2 = g_csrc[start + j + 2];
        int s3 = g_csrc[start + j + 3];
        float r0[CH], r1[CH], r2[CH], r3[CH];
        vloadh<CH>(r0, fb + (long long)s0 * D);
        vloadh<CH>(r1, fb + (long long)s1 * D);
        vloadh<CH>(r2, fb + (long long)s2 * D);
        vloadh<CH>(r3, fb + (long long)s3 * D);
#pragma unroll
        for (int v = 0; v < CH; v++) acc[v] += r0[v];
#pragma unroll
        for (int v = 0; v < CH; v++) acc[v] += r1[v];
#pragma unroll
        for (int v = 0; v < CH; v++) acc[v] += r2[v];
#pragma unroll
        for (int v = 0; v < CH; v++) acc[v] += r3[v];
    }
    for (; j < dg; j++) {
        int s0 = g_csrc[start + j];
        float r0[CH];
        vloadh<CH>(r0, fb + (long long)s0 * D);
#pragma unroll
        for (int v = 0; v < CH; v++) acc[v] += r0[v];
    }

    float inv = (dg > 0) ? (1.0f / (float)dg) : 0.0f;
#pragma unroll
    for (int v = 0; v < CH; v++) acc[v] *= inv;
    if (ADD_EXTRA) {
        float ex[CH];
        vload<CH>(ex, extra + (long long)warp * D + lane * CH);
#pragma unroll
        for (int v = 0; v < CH; v++) acc[v] += ex[v];
    }
    if (OUTH)
        vstoreh<CH>(outh + (long long)warp * D + lane * CH, acc);
    else
        vstore<CH>(outf + (long long)warp * D + lane * CH, acc);
}

// W[K,N] fp32 -> Wt[N,K] fp16 hi + fp16 lo (lossless to ~2^-22)
__global__ void k_wsplit(const float* __restrict__ W,
                         __half* __restrict__ th,
                         __half* __restrict__ tl, int K, int N) {
    int i = blockIdx.x * blockDim.x + threadIdx.x;
    if (i < K * N) {
        int k = i / N, n = i % N;
        float v = W[i];
        __half h = __float2half_rn(v);
        th[n * K + k] = h;
        tl[n * K + k] = __float2half_rn(v - __half2float(h));
    }
}

// ---------------- mma.sync fp16 GEMM, BM=128 BN=64, double-buffered ----------
// A fp16 (exact operand, no split). B = Wh + Wl fp16 pair.
// Per tile: acc += A*Bh + A*Bl -> 16 MMAs (was 24 with bf16 3-term split).
// F16ONLY: epilogue writes fp16 table only. DUAL: [0,64)->Th fp16, [64,128)->C2.
#define ASTR 40
#define OA  0
#define OBH 10240
#define OBL 15360
#define BUFB 20480
template <int KTOT, int NOUT, int NMAT, bool HAS_BIAS, bool BN, bool DUAL, bool F16ONLY>
__global__ void __launch_bounds__(256) k_mgemm(
    const __half* __restrict__ A1, const __half* __restrict__ A2,
    const __half* __restrict__ B1h, const __half* __restrict__ B1l,
    const __half* __restrict__ B2h, const __half* __restrict__ B2l,
    const float* __restrict__ bias, const float* __restrict__ gamma,
    const float* __restrict__ beta, const float* __restrict__ rm,
    const float* __restrict__ rv,
    float* __restrict__ C2, __half* __restrict__ Th) {
    extern __shared__ __align__(16) char dsm[];

    const int tid = threadIdx.x;
    const int lane = tid & 31;
    const int wid = tid >> 5;
    const int wm = wid & 3;
    const int wn = wid >> 2;
    const long long bm = (long long)blockIdx.y * 128;
    const int bn = blockIdx.x * 64;
    const int KC = KTOT / 32;
    const int TOT = NMAT * KC;

    float acc[2][4][4];
#pragma unroll
    for (int i = 0; i < 2; i++)
#pragma unroll
        for (int j = 0; j < 4; j++)
#pragma unroll
            for (int q = 0; q < 4; q++) acc[i][j][q] = 0.0f;

    const uint32_t sb = smem_u32(dsm);
    const uint32_t loA = (((wm * 32 + (lane & 15)) * ASTR + ((lane >> 4) << 3)) << 1);
    const uint32_t loB = (((wn * 32 + (lane & 7)) * ASTR + (((lane >> 3) & 1) << 3)) << 1);

    uint4 aR[2];   // A tile: 128x32 fp16 = 8KB; 256 thr x 2 x 16B
    uint4 bhR, blR;

#define LOAD_ITER(it) do {                                                       \
    int _m = (it) / KC, _kc = (it) % KC, _k0 = _kc * 32;                         \
    const __half* _A = (_m == 0) ? A1 : A2;                                      \
    const __half* _Bh = (_m == 0) ? B1h : B2h;                                   \
    const __half* _Bl = (_m == 0) ? B1l : B2l;                                   \
    _Pragma("unroll")                                                            \
    for (int _i = 0; _i < 2; _i++) {                                             \
        int _s = tid + _i * 256;                                                 \
        int _r = _s >> 2, _c = _s & 3;                                           \
        long long _grow = bm + _r;                                               \
        uint4 _v = make_uint4(0, 0, 0, 0);                                       \
        if (_grow < NN) _v = *(const uint4*)(_A + _grow * KTOT + _k0 + _c * 8);  \
        aR[_i] = _v;                                                             \
    }                                                                            \
    {                                                                            \
        int _r = tid >> 2, _c = tid & 3;                                         \
        long long _off = (long long)(bn + _r) * KTOT + _k0 + _c * 8;             \
        bhR = *(const uint4*)(_Bh + _off);                                       \
        blR = *(const uint4*)(_Bl + _off);                                       \
    }                                                                            \
} while (0)

#define STORE_ITER(buf) do {                                                     \
    char* _S = dsm + (buf) * BUFB;                                               \
    _Pragma("unroll")                                                            \
    for (int _i = 0; _i < 2; _i++) {                                             \
        int _s = tid + _i * 256;                                                 \
        int _r = _s >> 2, _c = _s & 3;                                           \
        *(uint4*)(_S + OA + (_r * ASTR + _c * 8) * 2) = aR[_i];                  \
    }                                                                            \
    {                                                                            \
        int _r = tid >> 2, _c = tid & 3;                                         \
        *(uint4*)(_S + OBH + (_r * ASTR + _c * 8) * 2) = bhR;                    \
        *(uint4*)(_S + OBL + (_r * ASTR + _c * 8) * 2) = blR;                    \
    }                                                                            \
} while (0)

#define COMPUTE(buf) do {                                                        \
    const uint32_t _b = sb + (buf) * BUFB;                                       \
    const uint32_t _aA = _b + OA + loA;                                          \
    const uint32_t _aBh = _b + OBH + loB;                                        \
    const uint32_t _aBl = _b + OBL + loB;                                        \
    _Pragma("unroll")                                                            \
    for (int _ka = 0; _ka < 2; _ka++) {                                          \
        const uint32_t _ko = _ka * 32;                                           \
        uint32_t _ah[2][4], _bh[4][2], _bl[4][2];                                \
        LDSM4(_ah[0], _aA + _ko);                                                \
        LDSM4(_ah[1], _aA + 1280 + _ko);                                         \
        _Pragma("unroll")                                                        \
        for (int _na = 0; _na < 4; _na++) {                                      \
            LDSM2(_bh[_na], _aBh + _na * 640 + _ko);                             \
            LDSM2(_bl[_na], _aBl + _na * 640 + _ko);                             \
        }                                                                        \
        _Pragma("unroll")                                                        \
        for (int _ma = 0; _ma < 2; _ma++)                                        \
            _Pragma("unroll")                                                    \
            for (int _na = 0; _na < 4; _na++) {                                  \
                MMA16816(acc[_ma][_na], _ah[_ma], _bh[_na]);                     \
                MMA16816(acc[_ma][_na], _ah[_ma], _bl[_na]);                     \
            }                                                                    \
    }                                                                            \
} while (0)

    LOAD_ITER(0);
    STORE_ITER(0);
    __syncthreads();
    for (int it = 0; it < TOT; it++) {
        const int cur = it & 1;
        if (it + 1 < TOT) LOAD_ITER(it + 1);
        COMPUTE(cur);
        if (it + 1 < TOT) STORE_ITER(cur ^ 1);
        __syncthreads();
    }

    const int g = lane >> 2, t = lane & 3;
#pragma unroll
    for (int ma = 0; ma < 2; ma++) {
#pragma unroll
        for (int na = 0; na < 4; na++) {
            int lcol = wn * 32 + na * 8 + 2 * t;
            int gc = bn + lcol;
#pragma unroll
            for (int half = 0; half < 2; half++) {
                long long row = bm + wm * 32 + ma * 16 + g + half * 8;
                if (row >= NN) continue;
                float v0 = acc[ma][na][half * 2 + 0];
                float v1 = acc[ma][na][half * 2 + 1];
                if (DUAL) {
                    if (gc < 64) {
                        *(__half2*)&Th[row * 64 + gc] = __floats2half2_rn(v0, v1);
                    } else {
                        C2[row * 64 + gc - 64] = v0 + bias[gc - 64];
                        C2[row * 64 + gc - 63] = v1 + bias[gc - 63];
                    }
                } else {
                    if (HAS_BIAS) { v0 += bias[gc]; v1 += bias[gc + 1]; }
                    if (BN) {
                        v0 = (v0 - rm[gc]) * rsqrtf(rv[gc] + FEPS) * gamma[gc] + beta[gc];
                        v1 = (v1 - rm[gc + 1]) * rsqrtf(rv[gc + 1] + FEPS) * gamma[gc + 1] + beta[gc + 1];
                        v0 = fmaxf(v0, 0.0f);
                        v1 = fmaxf(v1, 0.0f);
                    }
                    *(__half2*)&Th[row * NOUT + gc] = __floats2half2_rn(v0, v1);
                }
            }
        }
    }
#undef LOAD_ITER
#undef STORE_ITER
#undef COMPUTE
}

// ---------------- launch ----------------------------------------------------
extern "C" void kernel_launch(void* const* d_in, const int* in_sizes, int n_in,
                              void* d_out, int out_size) {
    const float* x    = (const float*)d_in[0];
    const void*  eidx = d_in[1];
    const float* W1l  = (const float*)d_in[2];
    const float* b1l  = (const float*)d_in[3];
    const float* W1r  = (const float*)d_in[4];
    const float* g1   = (const float*)d_in[5];
    const float* be1  = (const float*)d_in[6];
    const float* rm1  = (const float*)d_in[7];
    const float* rv1  = (const float*)d_in[8];
    const float* W2l  = (const float*)d_in[9];
    const float* b2l  = (const float*)d_in[10];
    const float* W2r  = (const float*)d_in[11];
    const float* g2   = (const float*)d_in[12];
    const float* be2  = (const float*)d_in[13];
    const float* rm2  = (const float*)d_in[14];
    const float* rv2  = (const float*)d_in[15];
    const float* Wcl  = (const float*)d_in[16];
    const float* bcl  = (const float*)d_in[17];
    const float* Wcr  = (const float*)d_in[18];
    float* out = (float*)d_out;

    int* p_degi;    cudaGetSymbolAddress((void**)&p_degi, g_degi);
    float* p_r;     cudaGetSymbolAddress((void**)&p_r, g_r);
    __half* p_xh;   cudaGetSymbolAddress((void**)&p_xh, g_xh);
    __half* p_msgh; cudaGetSymbolAddress((void**)&p_msgh, g_msgh);
    __half* p_h1h;  cudaGetSymbolAddress((void**)&p_h1h, g_h1h);
    __half* p_h2h;  cudaGetSymbolAddress((void**)&p_h2h, g_h2h);
    __half* p_th;   cudaGetSymbolAddress((void**)&p_th, g_th);
    __half* wh;     cudaGetSymbolAddress((void**)&wh, g_wh);
    __half* wl;     cudaGetSymbolAddress((void**)&wl, g_wl);

    const int DSMEM = 2 * BUFB;  // 40960
    cudaFuncSetAttribute(k_mgemm<INC, HIDC, 2, true, true, false, true>,
                         cudaFuncAttributeMaxDynamicSharedMemorySize, DSMEM);
    cudaFuncSetAttribute(k_mgemm<HIDC, HIDC, 2, true, true, false, true>,
                         cudaFuncAttributeMaxDynamicSharedMemorySize, DSMEM);
    cudaFuncSetAttribute(k_mgemm<HIDC, 128, 1, true, false, true, false>,
                         cudaFuncAttributeMaxDynamicSharedMemorySize, DSMEM);

    // 0) CSR build
    k_zero_detect<<<NBLK1, 256>>>(p_degi, NN, (const int*)eidx);
    k_degi<<<(EE + 255) / 256, 256>>>(eidx);
    k_scan1<<<NBLK1, 256>>>();
    k_scan2<<<1, 512>>>();
    k_scan3<<<NBLK1, 256>>>();
    k_fill<<<(EE + 255) / 256, 256>>>(eidx);

    // 1) weight transpose + fp16 split; x -> fp16 table
    k_wsplit<<<(INC * HIDC + 255) / 256, 256>>>(W1l, wh + WO_1L, wl + WO_1L, INC, HIDC);
    k_wsplit<<<(INC * HIDC + 255) / 256, 256>>>(W1r, wh + WO_1R, wl + WO_1R, INC, HIDC);
    k_wsplit<<<(HIDC * HIDC + 255) / 256, 256>>>(W2l, wh + WO_2L, wl + WO_2L, HIDC, HIDC);
    k_wsplit<<<(HIDC * HIDC + 255) / 256, 256>>>(W2r, wh + WO_2R, wl + WO_2R, HIDC, HIDC);
    k_wsplit<<<(HIDC * OUTC + 255) / 256, 256>>>(Wcl, wh + WO_CL, wl + WO_CL, HIDC, OUTC);
    k_wsplit<<<(HIDC * OUTC + 255) / 256, 256>>>(Wcr, wh + WO_CR, wl + WO_CR, HIDC, OUTC);
    k_tohalf<<<4096, 256>>>(x, p_xh, (long long)NN * INC / 2);

    const int MBLK = (NN + 127) / 128;  // 782
    const int AGG_BLOCKS = (NN + 7) / 8;

    // 2) layer 1
    k_agg<INC / 32, true, false><<<AGG_BLOCKS, 256>>>(p_xh, nullptr, p_msgh, nullptr);
    k_mgemm<INC, HIDC, 2, true, true, false, true><<<dim3(HIDC / 64, MBLK), 256, DSMEM>>>(
        p_msgh, p_xh, wh + WO_1L, wl + WO_1L, wh + WO_1R, wl + WO_1R,
        b1l, g1, be1, rm1, rv1, nullptr, p_h1h);

    // 3) layer 2
    k_agg<HIDC / 32, true, false><<<AGG_BLOCKS, 256>>>(p_h1h, nullptr, p_msgh, nullptr);
    k_mgemm<HIDC, HIDC, 2, true, true, false, true><<<dim3(HIDC / 64, MBLK), 256, DSMEM>>>(
        p_msgh, p_h1h, wh + WO_2L, wl + WO_2L, wh + WO_2R, wl + WO_2R,
        b2l, g2, be2, rm2, rv2, nullptr, p_h2h);

    // 4) layer 3: dual GEMM (t -> fp16 th, r = h2@Wcr + bcl fp32); out = agg(t)+r
    k_mgemm<HIDC, 128, 1, true, false, true, false><<<dim3(2, MBLK), 256, DSMEM>>>(
        p_h2h, nullptr, wh + WO_CL, wl + WO_CL, nullptr, nullptr,
        bcl, nullptr, nullptr, nullptr, nullptr, p_r, p_th);
    k_agg<OUTC / 32, false, true><<<AGG_BLOCKS, 256>>>(p_th, p_r, nullptr, out);
}

// round 13
// speedup vs baseline: 1.8167x; 1.1679x over previous
#include <cuda_runtime.h>
#include <cuda_fp16.h>
#include <cstdint>

#define NN 100000
#define EE 1600000
#define INC 128
#define HIDC 256
#define OUTC 64
#define FEPS 1e-5f
#define NBLK1 ((NN + 255) / 256)

// ---------------- scratch ----------------------------------------------------
__device__ int   g_is64;
__device__ int   g_degi[NN];
__device__ int   g_incl[NN];
__device__ int   g_bsum[512];
__device__ int   g_boff[512];
__device__ int   g_rowptr[NN];
__device__ int   g_cursor[NN];
__device__ int   g_csrc[EE];
__device__ float g_r[(size_t)NN * OUTC];
// fp16 tables (entire inter-kernel dataflow)
__device__ __half g_xh[(size_t)NN * INC];
__device__ __half g_msgh[(size_t)NN * HIDC];
__device__ __half g_h1h[(size_t)NN * HIDC];
__device__ __half g_h2h[(size_t)NN * HIDC];
__device__ __half g_th[(size_t)NN * OUTC];
// transposed weights, [N][K] layout, fp16 hi (+ fp16 lo used by layer 3 only)
#define WO_1L 0
#define WO_1R 32768
#define WO_2L 65536
#define WO_2R 131072
#define WO_CL 196608
#define WO_CR 212992
__device__ __half g_wh[229376];
__device__ __half g_wl[229376];

// ---------------- PTX helpers ------------------------------------------------
__device__ __forceinline__ uint32_t smem_u32(const void* p) {
    uint32_t a;
    asm("{ .reg .u64 t; cvta.to.shared.u64 t, %1; cvt.u32.u64 %0, t; }"
        : "=r"(a) : "l"(p));
    return a;
}
#define LDSM4(r, addr)                                                          \
    asm volatile("ldmatrix.sync.aligned.m8n8.x4.shared.b16 {%0,%1,%2,%3}, [%4];"\
                 : "=r"((r)[0]), "=r"((r)[1]), "=r"((r)[2]), "=r"((r)[3])       \
                 : "r"(addr))
#define LDSM2(r, addr)                                                          \
    asm volatile("ldmatrix.sync.aligned.m8n8.x2.shared.b16 {%0,%1}, [%2];"      \
                 : "=r"((r)[0]), "=r"((r)[1]) : "r"(addr))
#define MMA16816(d, a, b)                                                       \
    asm volatile("mma.sync.aligned.m16n8k16.row.col.f32.f16.f16.f32 "           \
                 "{%0,%1,%2,%3}, {%4,%5,%6,%7}, {%8,%9}, {%0,%1,%2,%3};"        \
                 : "+f"((d)[0]), "+f"((d)[1]), "+f"((d)[2]), "+f"((d)[3])       \
                 : "r"((a)[0]), "r"((a)[1]), "r"((a)[2]), "r"((a)[3]),          \
                   "r"((b)[0]), "r"((b)[1]))

// ---------------- misc kernels ----------------------------------------------
__device__ __forceinline__ int load_idx(const void* base, long long i) {
    if (g_is64) return (int)((const long long*)base)[i];
    return ((const int*)base)[i];
}
__global__ void k_zero_detect(int* p, int n, const int* e32) {
    int i = blockIdx.x * blockDim.x + threadIdx.x;
    if (i < n) p[i] = 0;
    if (blockIdx.x == 0 && threadIdx.x == 0) {
        int is64 = 1;
        for (int q = 0; q < 32; q++)
            if (e32[2 * q + 1] != 0) is64 = 0;
        g_is64 = is64;
    }
}
__global__ void k_degi(const void* eidx) {
    int e = blockIdx.x * blockDim.x + threadIdx.x;
    if (e < EE) atomicAdd(&g_degi[load_idx(eidx, (long long)EE + e)], 1);
}
__global__ void k_scan1() {
    __shared__ int s[256];
    int i = blockIdx.x * 256 + threadIdx.x;
    int v = (i < NN) ? g_degi[i] : 0;
    s[threadIdx.x] = v;
    __syncthreads();
#pragma unroll
    for (int off = 1; off < 256; off <<= 1) {
        int t = (threadIdx.x >= off) ? s[threadIdx.x - off] : 0;
        __syncthreads();
        s[threadIdx.x] += t;
        __syncthreads();
    }
    if (i < NN) g_incl[i] = s[threadIdx.x];
    if (threadIdx.x == 255) g_bsum[blockIdx.x] = s[255];
}
__global__ void k_scan2() {
    __shared__ int s[512];
    int tid = threadIdx.x;
    s[tid] = (tid < NBLK1) ? g_bsum[tid] : 0;
    __syncthreads();
#pragma unroll
    for (int off = 1; off < 512; off <<= 1) {
        int t = (tid >= off) ? s[tid - off] : 0;
        __syncthreads();
        s[tid] += t;
        __syncthreads();
    }
    g_boff[tid] = s[tid];
}
__global__ void k_scan3() {
    int i = blockIdx.x * 256 + threadIdx.x;
    if (i < NN) {
        int off = (blockIdx.x > 0) ? g_boff[blockIdx.x - 1] : 0;
        int start = off + g_incl[i] - g_degi[i];
        g_rowptr[i] = start;
        g_cursor[i] = start;
    }
}
__global__ void k_fill(const void* eidx) {
    int e = blockIdx.x * blockDim.x + threadIdx.x;
    if (e < EE) {
        int s = load_idx(eidx, e);
        int d = load_idx(eidx, (long long)EE + e);
        g_csrc[atomicAdd(&g_cursor[d], 1)] = s;
    }
}
__global__ void k_tohalf(const float* __restrict__ in, __half* __restrict__ out,
                         long long n2) {
    long long i = (long long)blockIdx.x * blockDim.x + threadIdx.x;
    long long stride = (long long)gridDim.x * blockDim.x;
    const float2* in2 = (const float2*)in;
    __half2* out2 = (__half2*)out;
    for (; i < n2; i += stride) out2[i] = __float22half2_rn(in2[i]);
}
// all 6 weight transposes + fp16 hi/lo splits in ONE kernel
__global__ void k_wsplit_all(const float* __restrict__ W1l, const float* __restrict__ W1r,
                             const float* __restrict__ W2l, const float* __restrict__ W2r,
                             const float* __restrict__ Wcl, const float* __restrict__ Wcr,
                             __half* __restrict__ wh, __half* __restrict__ wl) {
    int i = blockIdx.x * 256 + threadIdx.x;
    const float* W;
    int K, N, off, base;
    if (i < 32768)       { W = W1l; K = INC;  N = HIDC; off = WO_1L; base = i; }
    else if (i < 65536)  { W = W1r; K = INC;  N = HIDC; off = WO_1R; base = i - 32768; }
    else if (i < 131072) { W = W2l; K = HIDC; N = HIDC; off = WO_2L; base = i - 65536; }
    else if (i < 196608) { W = W2r; K = HIDC; N = HIDC; off = WO_2R; base = i - 131072; }
    else if (i < 212992) { W = Wcl; K = HIDC; N = OUTC; off = WO_CL; base = i - 196608; }
    else if (i < 229376) { W = Wcr; K = HIDC; N = OUTC; off = WO_CR; base = i - 212992; }
    else return;
    int k = base / N, n = base % N;
    float v = W[base];
    __half h = __float2half_rn(v);
    wh[off + n * K + k] = h;
    wl[off + n * K + k] = __float2half_rn(v - __half2float(h));
}

// ---------------- gather mean aggregation (fp16 in, fp16 or fp32 out) --------
template <int CH>
__device__ __forceinline__ void vloadh(float (&r)[CH], const __half* p) {
    uint32_t u[CH / 2];
    if (CH == 2) {
        u[0] = *(const uint32_t*)p;
    } else if (CH == 4) {
        uint2 v = *(const uint2*)p;
        u[0] = v.x; u[1] = v.y;
    } else {
        uint4 v = *(const uint4*)p;
        u[0] = v.x; u[1] = v.y; u[2] = v.z; u[3] = v.w;
    }
#pragma unroll
    for (int q = 0; q < CH / 2; q++) {
        __half2 h = *(__half2*)&u[q];
        float2 f = __half22float2(h);
        r[2 * q + 0] = f.x;
        r[2 * q + 1] = f.y;
    }
}
template <int CH>
__device__ __forceinline__ void vload(float (&r)[CH], const float* p) {
    if (CH == 2) {
        float2 v = *(const float2*)p;
        r[0] = v.x; r[1] = v.y;
    } else {
#pragma unroll
        for (int q = 0; q < CH / 4; q++) {
            float4 v = *(const float4*)(p + q * 4);
            r[q * 4 + 0] = v.x; r[q * 4 + 1] = v.y;
            r[q * 4 + 2] = v.z; r[q * 4 + 3] = v.w;
        }
    }
}
template <int CH>
__device__ __forceinline__ void vstore(float* p, const float (&r)[CH]) {
    if (CH == 2) {
        *(float2*)p = make_float2(r[0], r[1]);
    } else {
#pragma unroll
        for (int q = 0; q < CH / 4; q++)
            *(float4*)(p + q * 4) =
                make_float4(r[q * 4 + 0], r[q * 4 + 1], r[q * 4 + 2], r[q * 4 + 3]);
    }
}
template <int CH>
__device__ __forceinline__ void vstoreh(__half* p, const float (&r)[CH]) {
    uint32_t u[CH / 2];
#pragma unroll
    for (int q = 0; q < CH / 2; q++) {
        __half2 h = __floats2half2_rn(r[2 * q + 0], r[2 * q + 1]);
        u[q] = *(uint32_t*)&h;
    }
    if (CH == 2) {
        *(uint32_t*)p = u[0];
    } else if (CH == 4) {
        *(uint2*)p = make_uint2(u[0], u[1]);
    } else {
        *(uint4*)p = make_uint4(u[0], u[1], u[2], u[3]);
    }
}

template <int CH, bool OUTH, bool ADD_EXTRA>
__global__ void k_agg(const __half* __restrict__ feat,
                      const float* __restrict__ extra,
                      __half* __restrict__ outh,
                      float* __restrict__ outf) {
    const int D = 32 * CH;
    int warp = (blockIdx.x * blockDim.x + threadIdx.x) >> 5;
    int lane = threadIdx.x & 31;
    if (warp >= NN) return;
    int start = g_rowptr[warp];
    int dg = g_degi[warp];
    const __half* fb = feat + lane * CH;

    float acc[CH];
#pragma unroll
    for (int v = 0; v < CH; v++) acc[v] = 0.0f;

    int j = 0;
    for (; j + 4 <= dg; j += 4) {
        int s0 = g_csrc[start + j + 0];
        int s1 = g_csrc[start + j + 1];
        int s2 = g_csrc[start + j + 2];
        int s3 = g_csrc[start + j + 3];
        float r0[CH], r1[CH], r2[CH], r3[CH];
        vloadh<CH>(r0, fb + (long long)s0 * D);
        vloadh<CH>(r1, fb + (long long)s1 * D);
        vloadh<CH>(r2, fb + (long long)s2 * D);
        vloadh<CH>(r3, fb + (long long)s3 * D);
#pragma unroll
        for (int v = 0; v < CH; v++) acc[v] += r0[v];
#pragma unroll
        for (int v = 0; v < CH; v++) acc[v] += r1[v];
#pragma unroll
        for (int v = 0; v < CH; v++) acc[v] += r2[v];
#pragma unroll
        for (int v = 0; v < CH; v++) acc[v] += r3[v];
    }
    for (; j < dg; j++) {
        int s0 = g_csrc[start + j];
        float r0[CH];
        vloadh<CH>(r0, fb + (long long)s0 * D);
#pragma unroll
        for (int v = 0; v < CH; v++) acc[v] += r0[v];
    }

    float inv = (dg > 0) ? (1.0f / (float)dg) : 0.0f;
#pragma unroll
    for (int v = 0; v < CH; v++) acc[v] *= inv;
    if (ADD_EXTRA) {
        float ex[CH];
        vload<CH>(ex, extra + (long long)warp * D + lane * CH);
#pragma unroll
        for (int v = 0; v < CH; v++) acc[v] += ex[v];
    }
    if (OUTH)
        vstoreh<CH>(outh + (long long)warp * D + lane * CH, acc);
    else
        vstore<CH>(outf + (long long)warp * D + lane * CH, acc);
}

// ---------------- mma.sync fp16 GEMM, BM=128 BN=64, double-buffered ----------
// A fp16 exact. BLO: add A*Wl correction term (layer 3 only -> exact weights);
// layers 1-2 use Wh only (8 MMAs/tile, weight quant error ~2e-4 rms).
#define ASTR 40
template <int KTOT, int NOUT, int NMAT, bool HAS_BIAS, bool BN, bool DUAL, bool BLO>
__global__ void __launch_bounds__(256) k_mgemm(
    const __half* __restrict__ A1, const __half* __restrict__ A2,
    const __half* __restrict__ B1h, const __half* __restrict__ B1l,
    const __half* __restrict__ B2h, const __half* __restrict__ B2l,
    const float* __restrict__ bias, const float* __restrict__ gamma,
    const float* __restrict__ beta, const float* __restrict__ rm,
    const float* __restrict__ rv,
    float* __restrict__ C2, __half* __restrict__ Th) {
    extern __shared__ __align__(16) char dsm[];
    constexpr int OA = 0;
    constexpr int OBH = 10240;
    constexpr int OBL = 15360;
    constexpr int BUFB = BLO ? 20480 : 15360;

    const int tid = threadIdx.x;
    const int lane = tid & 31;
    const int wid = tid >> 5;
    const int wm = wid & 3;
    const int wn = wid >> 2;
    const long long bm = (long long)blockIdx.y * 128;
    const int bn = blockIdx.x * 64;
    const int KC = KTOT / 32;
    const int TOT = NMAT * KC;

    float acc[2][4][4];
#pragma unroll
    for (int i = 0; i < 2; i++)
#pragma unroll
        for (int j = 0; j < 4; j++)
#pragma unroll
            for (int q = 0; q < 4; q++) acc[i][j][q] = 0.0f;

    const uint32_t sb = smem_u32(dsm);
    const uint32_t loA = (((wm * 32 + (lane & 15)) * ASTR + ((lane >> 4) << 3)) << 1);
    const uint32_t loB = (((wn * 32 + (lane & 7)) * ASTR + (((lane >> 3) & 1) << 3)) << 1);

    uint4 aR[2];
    uint4 bhR, blR;

#define LOAD_ITER(it) do {                                                       \
    int _m = (it) / KC, _kc = (it) % KC, _k0 = _kc * 32;                         \
    const __half* _A = (_m == 0) ? A1 : A2;                                      \
    const __half* _Bh = (_m == 0) ? B1h : B2h;                                   \
    _Pragma("unroll")                                                            \
    for (int _i = 0; _i < 2; _i++) {                                             \
        int _s = tid + _i * 256;                                                 \
        int _r = _s >> 2, _c = _s & 3;                                           \
        long long _grow = bm + _r;                                               \
        uint4 _v = make_uint4(0, 0, 0, 0);                                       \
        if (_grow < NN) _v = *(const uint4*)(_A + _grow * KTOT + _k0 + _c * 8);  \
        aR[_i] = _v;                                                             \
    }                                                                            \
    {                                                                            \
        int _r = tid >> 2, _c = tid & 3;                                         \
        long long _off = (long long)(bn + _r) * KTOT + _k0 + _c * 8;             \
        bhR = *(const uint4*)(_Bh + _off);                                       \
        if (BLO) {                                                               \
            const __half* _Bl = (_m == 0) ? B1l : B2l;                           \
            blR = *(const uint4*)(_Bl + _off);                                   \
        }                                                                        \
    }                                                                            \
} while (0)

#define STORE_ITER(buf) do {                                                     \
    char* _S = dsm + (buf) * BUFB;                                               \
    _Pragma("unroll")                                                            \
    for (int _i = 0; _i < 2; _i++) {                                             \
        int _s = tid + _i * 256;                                                 \
        int _r = _s >> 2, _c = _s & 3;                                           \
        *(uint4*)(_S + OA + (_r * ASTR + _c * 8) * 2) = aR[_i];                  \
    }                                                                            \
    {                                                                            \
        int _r = tid >> 2, _c = tid & 3;                                         \
        *(uint4*)(_S + OBH + (_r * ASTR + _c * 8) * 2) = bhR;                    \
        if (BLO) *(uint4*)(_S + OBL + (_r * ASTR + _c * 8) * 2) = blR;           \
    }                                                                            \
} while (0)

#define COMPUTE(buf) do {                                                        \
    const uint32_t _b = sb + (buf) * BUFB;                                       \
    const uint32_t _aA = _b + OA + loA;                                          \
    const uint32_t _aBh = _b + OBH + loB;                                        \
    const uint32_t _aBl = _b + OBL + loB;                                        \
    _Pragma("unroll")                                                            \
    for (int _ka = 0; _ka < 2; _ka++) {                                          \
        const uint32_t _ko = _ka * 32;                                           \
        uint32_t _ah[2][4], _bh[4][2], _bl[4][2];                                \
        LDSM4(_ah[0], _aA + _ko);                                                \
        LDSM4(_ah[1], _aA + 1280 + _ko);                                         \
        _Pragma("unroll")                                                        \
        for (int _na = 0; _na < 4; _na++) {                                      \
            LDSM2(_bh[_na], _aBh + _na * 640 + _ko);                             \
            if (BLO) LDSM2(_bl[_na], _aBl + _na * 640 + _ko);                    \
        }                                                                        \
        _Pragma("unroll")                                                        \
        for (int _ma = 0; _ma < 2; _ma++)                                        \
            _Pragma("unroll")                                                    \
            for (int _na = 0; _na < 4; _na++) {                                  \
                MMA16816(acc[_ma][_na], _ah[_ma], _bh[_na]);                     \
                if (BLO) MMA16816(acc[_ma][_na], _ah[_ma], _bl[_na]);            \
            }                                                                    \
    }                                                                            \
} while (0)

    LOAD_ITER(0);
    STORE_ITER(0);
    __syncthreads();
    for (int it = 0; it < TOT; it++) {
        const int cur = it & 1;
        if (it + 1 < TOT) LOAD_ITER(it + 1);
        COMPUTE(cur);
        if (it + 1 < TOT) STORE_ITER(cur ^ 1);
        __syncthreads();
    }

    const int g = lane >> 2, t = lane & 3;
#pragma unroll
    for (int ma = 0; ma < 2; ma++) {
#pragma unroll
        for (int na = 0; na < 4; na++) {
            int lcol = wn * 32 + na * 8 + 2 * t;
            int gc = bn + lcol;
#pragma unroll
            for (int half = 0; half < 2; half++) {
                long long row = bm + wm * 32 + ma * 16 + g + half * 8;
                if (row >= NN) continue;
                float v0 = acc[ma][na][half * 2 + 0];
                float v1 = acc[ma][na][half * 2 + 1];
                if (DUAL) {
                    if (gc < 64) {
                        *(__half2*)&Th[row * 64 + gc] = __floats2half2_rn(v0, v1);
                    } else {
                        C2[row * 64 + gc - 64] = v0 + bias[gc - 64];
                        C2[row * 64 + gc - 63] = v1 + bias[gc - 63];
                    }
                } else {
                    if (HAS_BIAS) { v0 += bias[gc]; v1 += bias[gc + 1]; }
                    if (BN) {
                        v0 = (v0 - rm[gc]) * rsqrtf(rv[gc] + FEPS) * gamma[gc] + beta[gc];
                        v1 = (v1 - rm[gc + 1]) * rsqrtf(rv[gc + 1] + FEPS) * gamma[gc + 1] + beta[gc + 1];
                        v0 = fmaxf(v0, 0.0f);
                        v1 = fmaxf(v1, 0.0f);
                    }
                    *(__half2*)&Th[row * NOUT + gc] = __floats2half2_rn(v0, v1);
                }
            }
        }
    }
#undef LOAD_ITER
#undef STORE_ITER
#undef COMPUTE
}

// ---------------- launch ----------------------------------------------------
extern "C" void kernel_launch(void* const* d_in, const int* in_sizes, int n_in,
                              void* d_out, int out_size) {
    const float* x    = (const float*)d_in[0];
    const void*  eidx = d_in[1];
    const float* W1l  = (const float*)d_in[2];
    const float* b1l  = (const float*)d_in[3];
    const float* W1r  = (const float*)d_in[4];
    const float* g1   = (const float*)d_in[5];
    const float* be1  = (const float*)d_in[6];
    const float* rm1  = (const float*)d_in[7];
    const float* rv1  = (const float*)d_in[8];
    const float* W2l  = (const float*)d_in[9];
    const float* b2l  = (const float*)d_in[10];
    const float* W2r  = (const float*)d_in[11];
    const float* g2   = (const float*)d_in[12];
    const float* be2  = (const float*)d_in[13];
    const float* rm2  = (const float*)d_in[14];
    const float* rv2  = (const float*)d_in[15];
    const float* Wcl  = (const float*)d_in[16];
    const float* bcl  = (const float*)d_in[17];
    const float* Wcr  = (const float*)d_in[18];
    float* out = (float*)d_out;

    int* p_degi;    cudaGetSymbolAddress((void**)&p_degi, g_degi);
    float* p_r;     cudaGetSymbolAddress((void**)&p_r, g_r);
    __half* p_xh;   cudaGetSymbolAddress((void**)&p_xh, g_xh);
    __half* p_msgh; cudaGetSymbolAddress((void**)&p_msgh, g_msgh);
    __half* p_h1h;  cudaGetSymbolAddress((void**)&p_h1h, g_h1h);
    __half* p_h2h;  cudaGetSymbolAddress((void**)&p_h2h, g_h2h);
    __half* p_th;   cudaGetSymbolAddress((void**)&p_th, g_th);
    __half* wh;     cudaGetSymbolAddress((void**)&wh, g_wh);
    __half* wl;     cudaGetSymbolAddress((void**)&wl, g_wl);

    const int DSMEM_HI = 2 * 15360;  // 30720 (layers 1-2, Wh only)
    const int DSMEM_LO = 2 * 20480;  // 40960 (layer 3, Wh+Wl)
    cudaFuncSetAttribute(k_mgemm<INC, HIDC, 2, true, true, false, false>,
                         cudaFuncAttributeMaxDynamicSharedMemorySize, DSMEM_HI);
    cudaFuncSetAttribute(k_mgemm<HIDC, HIDC, 2, true, true, false, false>,
                         cudaFuncAttributeMaxDynamicSharedMemorySize, DSMEM_HI);
    cudaFuncSetAttribute(k_mgemm<HIDC, 128, 1, true, false, true, true>,
                         cudaFuncAttributeMaxDynamicSharedMemorySize, DSMEM_LO);

    // 0) CSR build
    k_zero_detect<<<NBLK1, 256>>>(p_degi, NN, (const int*)eidx);
    k_degi<<<(EE + 255) / 256, 256>>>(eidx);
    k_scan1<<<NBLK1, 256>>>();
    k_scan2<<<1, 512>>>();
    k_scan3<<<NBLK1, 256>>>();
    k_fill<<<(EE + 255) / 256, 256>>>(eidx);

    // 1) all weight transposes/splits in one kernel; x -> fp16
    k_wsplit_all<<<(229376 + 255) / 256, 256>>>(W1l, W1r, W2l, W2r, Wcl, Wcr, wh, wl);
    k_tohalf<<<4096, 256>>>(x, p_xh, (long long)NN * INC / 2);

    const int MBLK = (NN + 127) / 128;  // 782
    const int AGG_BLOCKS = (NN + 7) / 8;

    // 2) layer 1 (Wh only)
    k_agg<INC / 32, true, false><<<AGG_BLOCKS, 256>>>(p_xh, nullptr, p_msgh, nullptr);
    k_mgemm<INC, HIDC, 2, true, true, false, false><<<dim3(HIDC / 64, MBLK), 256, DSMEM_HI>>>(
        p_msgh, p_xh, wh + WO_1L, nullptr, wh + WO_1R, nullptr,
        b1l, g1, be1, rm1, rv1, nullptr, p_h1h);

    // 3) layer 2 (Wh only)
    k_agg<HIDC / 32, true, false><<<AGG_BLOCKS, 256>>>(p_h1h, nullptr, p_msgh, nullptr);
    k_mgemm<HIDC, HIDC, 2, true, true, false, false><<<dim3(HIDC / 64, MBLK), 256, DSMEM_HI>>>(
        p_msgh, p_h1h, wh + WO_2L, nullptr, wh + WO_2R, nullptr,
        b2l, g2, be2, rm2, rv2, nullptr, p_h2h);

    // 4) layer 3 (exact Wh+Wl): dual GEMM, then out = agg(t) + r
    k_mgemm<HIDC, 128, 1, true, false, true, true><<<dim3(2, MBLK), 256, DSMEM_LO>>>(
        p_h2h, nullptr, wh + WO_CL, wl + WO_CL, nullptr, nullptr,
        bcl, nullptr, nullptr, nullptr, nullptr, p_r, p_th);
    k_agg<OUTC / 32, false, true><<<AGG_BLOCKS, 256>>>(p_th, p_r, nullptr, out);
}